// round 6
// baseline (speedup 1.0000x reference)
#include <cuda_runtime.h>
#include <cstdint>
#include <cstddef>
#include <math.h>

// ---------------------------------------------------------------------------
// Scratch (device globals -- no allocation allowed)
// ---------------------------------------------------------------------------
__device__ int          g_knn1[2 * 4096 * 16];
__device__ int          g_knn2[2 * 2048 * 16];
__device__ float        g_res1[2 * 4096 * 128];
__device__ float        g_part[4194304];        // split-K partials (16MB)
__device__ unsigned int g_W1hi[131072],  g_W1lo[131072];
__device__ unsigned int g_W2hi[262144],  g_W2lo[262144];
__device__ unsigned int g_chhi[1048576], g_chlo[1048576];
__device__ unsigned int g_ch1hi[1048576], g_ch1lo[1048576];

// ---------------------------------------------------------------------------
// helpers
// ---------------------------------------------------------------------------
__device__ __forceinline__ unsigned int to_tf32(float v) {
    unsigned int r;
    asm("cvt.rna.tf32.f32 %0, %1;" : "=r"(r) : "f"(v));
    return r;
}
__device__ __forceinline__ void split_tf32(float v, unsigned int& hi,
                                           unsigned int& lo) {
    hi = to_tf32(v);
    lo = to_tf32(v - __uint_as_float(hi));
}
__device__ __forceinline__ void mma_tf32(float c[4], const unsigned int a[4],
                                         const unsigned int b[2]) {
    asm("mma.sync.aligned.m16n8k8.row.col.f32.tf32.tf32.f32 "
        "{%0,%1,%2,%3}, {%4,%5,%6,%7}, {%8,%9}, {%0,%1,%2,%3};"
        : "+f"(c[0]), "+f"(c[1]), "+f"(c[2]), "+f"(c[3])
        : "r"(a[0]), "r"(a[1]), "r"(a[2]), "r"(a[3]), "r"(b[0]), "r"(b[1]));
}
__device__ __forceinline__ unsigned long long pack2(float x, float y) {
    unsigned long long r;
    asm("mov.b64 %0, {%1, %2};" : "=l"(r) : "f"(x), "f"(y));
    return r;
}
__device__ __forceinline__ unsigned long long add2(unsigned long long a,
                                                   unsigned long long b) {
    unsigned long long r;
    asm("add.rn.f32x2 %0, %1, %2;" : "=l"(r) : "l"(a), "l"(b));
    return r;
}
__device__ __forceinline__ unsigned long long mul2(unsigned long long a,
                                                   unsigned long long b) {
    unsigned long long r;
    asm("mul.rn.f32x2 %0, %1, %2;" : "=l"(r) : "l"(a), "l"(b));
    return r;
}

// ---------------------------------------------------------------------------
// prep: split W1, W2, ch into tf32 hi/lo planes
// ---------------------------------------------------------------------------
__global__ void __launch_bounds__(256) split_kernel(
    const float* __restrict__ W1, const float* __restrict__ W2,
    const float* __restrict__ ch)
{
    constexpr int N1 = 131072, N2 = 262144, N3 = 1048576;
    int i = blockIdx.x * 256 + threadIdx.x;
    const float* src;
    unsigned int *dh, *dl;
    int k;
    if (i < N1)           { src = W1; dh = g_W1hi; dl = g_W1lo; k = i; }
    else if (i < N1 + N2) { src = W2; dh = g_W2hi; dl = g_W2lo; k = i - N1; }
    else if (i < N1 + N2 + N3) { src = ch; dh = g_chhi; dl = g_chlo; k = i - N1 - N2; }
    else return;
    float v = __ldg(src + k);
    split_tf32(v, dh[k], dl[k]);
}

// ---------------------------------------------------------------------------
// KNN v5: both stages in one launch. Warp-per-center, negated-SoA smem tiles,
// packed f32x2 distance math (exactly rounds like scalar __fadd/__fmul rn).
// Lanes 0..15 hold sorted top-16 u64 keys ((dist_bits<<32)|idx); reproduces
// jax.lax.top_k(-d2) ordering (d asc, idx asc) exactly.
// ---------------------------------------------------------------------------
__global__ void __launch_bounds__(256) knn_kernel(
    const float* __restrict__ pos, int* __restrict__ knn1,
    int* __restrict__ knn2)
{
    constexpr int TILE = 1024;
    __shared__ __align__(16) float sn[3 * TILE];   // -x @0, -y @1024, -z @2048

    const int tid  = threadIdx.x;
    const int warp = tid >> 5;
    const int lane = tid & 31;

    int pstride, n_in, n_out, center;
    int* outp;
    if (blockIdx.x < 1024) {
        pstride = 1; n_in = 8192; n_out = 4096; outp = knn1;
        center = blockIdx.x * 8 + warp;
    } else {
        pstride = 2; n_in = 4096; n_out = 2048; outp = knn2;
        center = (blockIdx.x - 1024) * 8 + warp;
    }
    const int b = center / n_out;
    const int n = center % n_out;

    const float* posb = pos + (size_t)b * 8192 * 3;
    const float cx = posb[(size_t)(n * 2 * pstride) * 3 + 0];
    const float cy = posb[(size_t)(n * 2 * pstride) * 3 + 1];
    const float cz = posb[(size_t)(n * 2 * pstride) * 3 + 2];
    const unsigned long long cxx = pack2(cx, cx);
    const unsigned long long cyy = pack2(cy, cy);
    const unsigned long long czz = pack2(cz, cz);

    unsigned long long lkey   = 0x7F800000FFFFFFFFull;
    unsigned long long thresh = 0x7F800000FFFFFFFFull;
    float tf = __int_as_float(0x7F800000);

    const int nTiles = n_in / TILE;
    float v[12];

#pragma unroll
    for (int k = 0; k < 4; k++) {
        int p = k * 256 + tid;
#pragma unroll
        for (int d = 0; d < 3; d++)
            v[3 * k + d] = __ldg(posb + (size_t)p * pstride * 3 + d);
    }

    for (int t = 0; t < nTiles; t++) {
#pragma unroll
        for (int k = 0; k < 4; k++) {
            int p = k * 256 + tid;
            sn[p]        = -v[3 * k];
            sn[p + 1024] = -v[3 * k + 1];
            sn[p + 2048] = -v[3 * k + 2];
        }
        __syncthreads();
        if (t + 1 < nTiles) {
            const int base = (t + 1) * TILE;
#pragma unroll
            for (int k = 0; k < 4; k++) {
                int p = base + k * 256 + tid;
#pragma unroll
                for (int d = 0; d < 3; d++)
                    v[3 * k + d] = __ldg(posb + (size_t)p * pstride * 3 + d);
            }
        }

        const int jbase = t * TILE;
#pragma unroll 4
        for (int it = 0; it < 16; ++it) {
            const int j = it * 64 + 2 * lane;
            unsigned long long nx = *(const unsigned long long*)(sn + j);
            unsigned long long ny = *(const unsigned long long*)(sn + 1024 + j);
            unsigned long long nz = *(const unsigned long long*)(sn + 2048 + j);
            unsigned long long ax = add2(cxx, nx);
            unsigned long long ay = add2(cyy, ny);
            unsigned long long az = add2(czz, nz);
            unsigned long long dp =
                add2(add2(mul2(ax, ax), mul2(ay, ay)), mul2(az, az));
            float d0, d1;
            asm("mov.b64 {%0, %1}, %2;" : "=f"(d0), "=f"(d1) : "l"(dp));
#pragma unroll
            for (int h = 0; h < 2; h++) {
                float dv = h ? d1 : d0;
                unsigned mask = __ballot_sync(0xffffffffu, dv <= tf);
                while (mask) {
                    const int src = __ffs(mask) - 1;
                    mask &= mask - 1;
                    float cd = __shfl_sync(0xffffffffu, dv, src);
                    unsigned idx = (unsigned)(jbase + it * 64 + 2 * src + h);
                    unsigned long long ck =
                        ((unsigned long long)__float_as_uint(cd) << 32) | idx;
                    if (ck < thresh) {   // uniform
                        unsigned long long up =
                            __shfl_up_sync(0xffffffffu, lkey, 1);
                        bool keep = (lkey < ck);
                        unsigned long long ins =
                            (lane == 0 || up < ck) ? ck : up;
                        lkey = keep ? lkey : ins;
                        thresh = __shfl_sync(0xffffffffu, lkey, 15);
                        tf = __uint_as_float((unsigned)(thresh >> 32));
                    }
                }
            }
        }
        __syncthreads();
    }

    if (lane < 16)
        outp[(size_t)center * 16 + lane] =
            (int)(unsigned)(lkey & 0xffffffffull);
}

// ---------------------------------------------------------------------------
// Gathered-conv GEMM on tensor cores, 3xTF32 from PRE-SPLIT hi/lo planes.
// 256 threads, BM=128 x BN=128, 8 warps (4M x 2N), k-major smem planes
// (stride 136 -> conflict-free fragment loads), double-buffered, split-K.
// ---------------------------------------------------------------------------
template <int CIN, int NSPLIT>
__global__ void __launch_bounds__(256, 2)
gconv_mma(const unsigned int* __restrict__ Ahi,
          const unsigned int* __restrict__ Alo,
          const int* __restrict__ knn,
          const unsigned int* __restrict__ Whi,
          const unsigned int* __restrict__ Wlo,
          float* __restrict__ part, int n_in, int n_out, int Mtot)
{
    constexpr int BM = 128, BN = 128, BK = 16, S = 136;
    constexpr int PLANE = BK * S;            // 2176 words
    constexpr int LOADSZ = 4 * PLANE;        // Ahi, Alo, Bhi, Blo
    constexpr int NPB = 16 / NSPLIT;
    constexpr int ITERS = NPB * CIN / BK;
    constexpr int KD = 16 * CIN;
    extern __shared__ unsigned int dynsm[];

    const int tid = threadIdx.x;
    const int split = blockIdx.y;
    const int m_base = blockIdx.x * BM;
    const int b = m_base / n_out;
    const int warp = tid >> 5, lane = tid & 31;
    const int g = lane >> 2, t = lane & 3;
    const int wm = (warp & 3) * 32, wn = (warp >> 2) * 64;

    const int arow = tid >> 1;              // 0..127 (A m-row / B n-row)
    const int aoff = (tid & 1) * 8;         // k offset
    const int* knnrow = knn + (size_t)(m_base + arow) * 16;
    const unsigned int* chh = Ahi + (size_t)b * n_in * CIN;
    const unsigned int* chl = Alo + (size_t)b * n_in * CIN;
    const unsigned int* wh = Whi + (size_t)arow * KD + split * NPB * CIN + aoff;
    const unsigned int* wl = Wlo + (size_t)arow * KD + split * NPB * CIN + aoff;

    float acc[2][8][4];
#pragma unroll
    for (int i = 0; i < 2; i++)
#pragma unroll
        for (int j = 0; j < 8; j++)
#pragma unroll
            for (int k = 0; k < 4; k++) acc[i][j][k] = 0.0f;

    unsigned int rah[8], ral[8], rbh[8], rbl[8];

    auto loadAB = [&](int it) {
        const int kn = split * NPB + (it * BK) / CIN;
        const int c0 = (it * BK) % CIN;
        const int j = __ldg(&knnrow[kn]);
        const unsigned int* pah = chh + (size_t)j * CIN + c0 + aoff;
        const unsigned int* pal = chl + (size_t)j * CIN + c0 + aoff;
#pragma unroll
        for (int q = 0; q < 4; q++) {
            uint2 h = *(const uint2*)(pah + 2 * q);
            uint2 l = *(const uint2*)(pal + 2 * q);
            rah[2 * q] = h.x; rah[2 * q + 1] = h.y;
            ral[2 * q] = l.x; ral[2 * q + 1] = l.y;
        }
        const unsigned int* pbh = wh + it * BK;
        const unsigned int* pbl = wl + it * BK;
#pragma unroll
        for (int q = 0; q < 4; q++) {
            uint2 h = *(const uint2*)(pbh + 2 * q);
            uint2 l = *(const uint2*)(pbl + 2 * q);
            rbh[2 * q] = h.x; rbh[2 * q + 1] = h.y;
            rbl[2 * q] = l.x; rbl[2 * q + 1] = l.y;
        }
    };
    auto storeAB = [&](int buf) {
        unsigned int* base = dynsm + buf * LOADSZ;
#pragma unroll
        for (int i = 0; i < 8; i++) {
            const int row = (aoff + i) * S + arow;
            base[row]             = rah[i];
            base[PLANE + row]     = ral[i];
            base[2 * PLANE + row] = rbh[i];
            base[3 * PLANE + row] = rbl[i];
        }
    };

    loadAB(0); storeAB(0);
    __syncthreads();
    int cur = 0;

    for (int it = 0; it < ITERS; ++it) {
        if (it + 1 < ITERS) { loadAB(it + 1); storeAB(cur ^ 1); }
        const unsigned int* Ah = dynsm + cur * LOADSZ;
        const unsigned int* Al = Ah + PLANE;
        const unsigned int* Bh = Ah + 2 * PLANE;
        const unsigned int* Bl = Ah + 3 * PLANE;
#pragma unroll
        for (int k0 = 0; k0 < BK; k0 += 8) {
            unsigned int Abf[2][4], Alf[2][4];
#pragma unroll
            for (int mt = 0; mt < 2; mt++) {
                const int r0 = wm + mt * 16 + g;
                const int ka = (k0 + t) * S, kb = (k0 + t + 4) * S;
                Abf[mt][0] = Ah[ka + r0];
                Abf[mt][1] = Ah[ka + r0 + 8];
                Abf[mt][2] = Ah[kb + r0];
                Abf[mt][3] = Ah[kb + r0 + 8];
                Alf[mt][0] = Al[ka + r0];
                Alf[mt][1] = Al[ka + r0 + 8];
                Alf[mt][2] = Al[kb + r0];
                Alf[mt][3] = Al[kb + r0 + 8];
            }
#pragma unroll
            for (int nt = 0; nt < 8; nt++) {
                const int nn = wn + nt * 8 + g;
                const int ka = (k0 + t) * S, kb = (k0 + t + 4) * S;
                unsigned int Bbf[2] = { Bh[ka + nn], Bh[kb + nn] };
                unsigned int Blf[2] = { Bl[ka + nn], Bl[kb + nn] };
#pragma unroll
                for (int mt = 0; mt < 2; mt++) {
                    mma_tf32(acc[mt][nt], Abf[mt], Bbf);
                    mma_tf32(acc[mt][nt], Abf[mt], Blf);
                    mma_tf32(acc[mt][nt], Alf[mt], Bbf);
                }
            }
        }
        __syncthreads();
        cur ^= 1;
    }

    float* dst = part + ((size_t)split * Mtot + m_base) * BN;
#pragma unroll
    for (int mt = 0; mt < 2; mt++)
#pragma unroll
        for (int nt = 0; nt < 8; nt++) {
            const int r = wm + mt * 16 + g;
            const int c = wn + nt * 8 + 2 * t;
            *(float2*)(dst + (size_t)r * BN + c) =
                make_float2(acc[mt][nt][0], acc[mt][nt][1]);
            *(float2*)(dst + (size_t)(r + 8) * BN + c) =
                make_float2(acc[mt][nt][2], acc[mt][nt][3]);
        }
}

// ---------------------------------------------------------------------------
// combine (mid): sum NSPLIT partials + bias + LN + SiLU -> tf32 hi/lo planes
// ---------------------------------------------------------------------------
template <int NSPLIT>
__global__ void __launch_bounds__(256) combine_mid(
    const float* __restrict__ part, int M,
    const float* __restrict__ bias, const float* __restrict__ gamma,
    const float* __restrict__ beta,
    unsigned int* __restrict__ outhi, unsigned int* __restrict__ outlo)
{
    const int lane = threadIdx.x & 31;
    const int row = blockIdx.x * 8 + (threadIdx.x >> 5);

    const float4* p4 = (const float4*)part;
    float4 x = p4[(size_t)row * 32 + lane];
#pragma unroll
    for (int s = 1; s < NSPLIT; s++) {
        float4 y = p4[((size_t)s * M + row) * 32 + lane];
        x.x += y.x; x.y += y.y; x.z += y.z; x.w += y.w;
    }
    float4 bb = *(const float4*)(bias + lane * 4);
    float4 gg = *(const float4*)(gamma + lane * 4);
    float4 be = *(const float4*)(beta + lane * 4);
    x.x += bb.x; x.y += bb.y; x.z += bb.z; x.w += bb.w;

    float s = x.x + x.y + x.z + x.w;
#pragma unroll
    for (int off = 16; off; off >>= 1) s += __shfl_xor_sync(~0u, s, off);
    float mu = s * (1.0f / 128.0f);
    float d0 = x.x - mu, d1 = x.y - mu, d2 = x.z - mu, d3 = x.w - mu;
    float s2 = d0 * d0 + d1 * d1 + d2 * d2 + d3 * d3;
#pragma unroll
    for (int off = 16; off; off >>= 1) s2 += __shfl_xor_sync(~0u, s2, off);
    float rstd = rsqrtf(s2 * (1.0f / 128.0f) + 1e-5f);

    float y0 = d0 * rstd * gg.x + be.x;
    float y1 = d1 * rstd * gg.y + be.y;
    float y2 = d2 * rstd * gg.z + be.z;
    float y3 = d3 * rstd * gg.w + be.w;
    y0 = y0 / (1.0f + expf(-y0));
    y1 = y1 / (1.0f + expf(-y1));
    y2 = y2 / (1.0f + expf(-y2));
    y3 = y3 / (1.0f + expf(-y3));

    uint4 h, l;
    split_tf32(y0, h.x, l.x);
    split_tf32(y1, h.y, l.y);
    split_tf32(y2, h.z, l.z);
    split_tf32(y3, h.w, l.w);
    ((uint4*)outhi)[(size_t)row * 32 + lane] = h;
    ((uint4*)outlo)[(size_t)row * 32 + lane] = l;
}

// ---------------------------------------------------------------------------
// combine (final): sum partials + bias + LN + SiLU + residual -> float out
// ---------------------------------------------------------------------------
template <int NSPLIT>
__global__ void __launch_bounds__(256) combine_final(
    const float* __restrict__ part, int M,
    const float* __restrict__ bias, const float* __restrict__ gamma,
    const float* __restrict__ beta, const float* __restrict__ res_in,
    float* __restrict__ out, int n_out)
{
    const int lane = threadIdx.x & 31;
    const int row = blockIdx.x * 8 + (threadIdx.x >> 5);

    const float4* p4 = (const float4*)part;
    float4 x = p4[(size_t)row * 32 + lane];
#pragma unroll
    for (int s = 1; s < NSPLIT; s++) {
        float4 y = p4[((size_t)s * M + row) * 32 + lane];
        x.x += y.x; x.y += y.y; x.z += y.z; x.w += y.w;
    }
    float4 bb = *(const float4*)(bias + lane * 4);
    float4 gg = *(const float4*)(gamma + lane * 4);
    float4 be = *(const float4*)(beta + lane * 4);
    x.x += bb.x; x.y += bb.y; x.z += bb.z; x.w += bb.w;

    float s = x.x + x.y + x.z + x.w;
#pragma unroll
    for (int off = 16; off; off >>= 1) s += __shfl_xor_sync(~0u, s, off);
    float mu = s * (1.0f / 128.0f);
    float d0 = x.x - mu, d1 = x.y - mu, d2 = x.z - mu, d3 = x.w - mu;
    float s2 = d0 * d0 + d1 * d1 + d2 * d2 + d3 * d3;
#pragma unroll
    for (int off = 16; off; off >>= 1) s2 += __shfl_xor_sync(~0u, s2, off);
    float rstd = rsqrtf(s2 * (1.0f / 128.0f) + 1e-5f);

    float y0 = d0 * rstd * gg.x + be.x;
    float y1 = d1 * rstd * gg.y + be.y;
    float y2 = d2 * rstd * gg.z + be.z;
    float y3 = d3 * rstd * gg.w + be.w;
    float4 o4;
    o4.x = y0 / (1.0f + expf(-y0));
    o4.y = y1 / (1.0f + expf(-y1));
    o4.z = y2 / (1.0f + expf(-y2));
    o4.w = y3 / (1.0f + expf(-y3));

    const int b2 = row / n_out;
    const int nn = row % n_out;
    const float4 rr = *(const float4*)(
        res_in + ((size_t)b2 * (2 * n_out) + 2 * nn) * 128 + lane * 4);
    o4.x += rr.x; o4.y += rr.y; o4.z += rr.z; o4.w += rr.w;
    ((float4*)out)[(size_t)row * 32 + lane] = o4;
}

// ---------------------------------------------------------------------------
// Residual path (stage 1): res1[b,n,:] = ch[b,2n,:] @ Wres + bres
// ---------------------------------------------------------------------------
__global__ void __launch_bounds__(128) res_kernel(
    const float* __restrict__ ch, const float* __restrict__ Wres,
    const float* __restrict__ bres, float* __restrict__ res1)
{
    __shared__ float s_w[64 * 128];
    __shared__ float s_ch[8][64];
    const int tid = threadIdx.x;
    const int m_base = blockIdx.x * 64;
    const int b = m_base / 4096;
    const int n_base = m_base % 4096;

    for (int i = tid; i < 64 * 128 / 4; i += 128)
        ((float4*)s_w)[i] = ((const float4*)Wres)[i];
    __syncthreads();

    const float bias = __ldg(&bres[tid]);
    const int rr = tid >> 4, q = tid & 15;

    for (int g = 0; g < 8; g++) {
        const float* src = ch +
            ((size_t)b * 8192 + 2 * (n_base + g * 8 + rr)) * 64 + q * 4;
        *(float4*)&s_ch[rr][q * 4] = *(const float4*)src;
        __syncthreads();
        float acc[8];
#pragma unroll
        for (int t = 0; t < 8; t++) acc[t] = bias;
        for (int c = 0; c < 64; c++) {
            float wv = s_w[c * 128 + tid];
#pragma unroll
            for (int t = 0; t < 8; t++) acc[t] += s_ch[t][c] * wv;
        }
#pragma unroll
        for (int t = 0; t < 8; t++)
            res1[(size_t)(m_base + g * 8 + t) * 128 + tid] = acc[t];
        __syncthreads();
    }
}

// ---------------------------------------------------------------------------
__global__ void poscopy_kernel(const float* __restrict__ pos,
                               float* __restrict__ out)
{
    int i = blockIdx.x * blockDim.x + threadIdx.x;
    if (i < 2 * 2048 * 3) {
        int b = i / 6144;
        int rem = i - b * 6144;
        int n = rem / 3;
        int d = rem - n * 3;
        out[i] = pos[((size_t)b * 8192 + 4 * n) * 3 + d];
    }
}

// ---------------------------------------------------------------------------
extern "C" void kernel_launch(void* const* d_in, const int* in_sizes, int n_in,
                              void* d_out, int out_size)
{
    const float* pos  = (const float*)d_in[0];
    const float* ch   = (const float*)d_in[1];
    const float* W1   = (const float*)d_in[2];
    const float* b1   = (const float*)d_in[3];
    const float* Wres = (const float*)d_in[4];
    const float* bres = (const float*)d_in[5];
    const float* W2   = (const float*)d_in[6];
    const float* b2   = (const float*)d_in[7];
    const float* g1   = (const float*)d_in[8];
    const float* be1  = (const float*)d_in[9];
    const float* g2   = (const float*)d_in[10];
    const float* be2  = (const float*)d_in[11];
    float* out = (float*)d_out;

    int *knn1p, *knn2p;
    float *res1p, *partp;
    unsigned int *w1h, *w1l, *w2h, *w2l, *chh, *chl, *c1h, *c1l;
    cudaGetSymbolAddress((void**)&knn1p, g_knn1);
    cudaGetSymbolAddress((void**)&knn2p, g_knn2);
    cudaGetSymbolAddress((void**)&res1p, g_res1);
    cudaGetSymbolAddress((void**)&partp, g_part);
    cudaGetSymbolAddress((void**)&w1h, g_W1hi);
    cudaGetSymbolAddress((void**)&w1l, g_W1lo);
    cudaGetSymbolAddress((void**)&w2h, g_W2hi);
    cudaGetSymbolAddress((void**)&w2l, g_W2lo);
    cudaGetSymbolAddress((void**)&chh, g_chhi);
    cudaGetSymbolAddress((void**)&chl, g_chlo);
    cudaGetSymbolAddress((void**)&c1h, g_ch1hi);
    cudaGetSymbolAddress((void**)&c1l, g_ch1lo);

    constexpr int SMEM = 2 * 4 * 16 * 136 * 4;   // 69632 bytes
    cudaFuncSetAttribute(gconv_mma<64, 4>,
                         cudaFuncAttributeMaxDynamicSharedMemorySize, SMEM);
    cudaFuncSetAttribute(gconv_mma<128, 8>,
                         cudaFuncAttributeMaxDynamicSharedMemorySize, SMEM);

    // prep: tf32 splits of W1, W2, ch
    split_kernel<<<5633, 256>>>(W1, W2, ch);
    // KNN (both stages, one launch)
    knn_kernel<<<1536, 256>>>(pos, knn1p, knn2p);
    // residual GEMM (stage 1)
    res_kernel<<<128, 128>>>(ch, Wres, bres, res1p);
    // conv1: split-K 4 -> partials -> combine (writes ch1 hi/lo splits)
    gconv_mma<64, 4><<<dim3(64, 4), 256, SMEM>>>(
        chh, chl, knn1p, w1h, w1l, partp, 8192, 4096, 8192);
    combine_mid<4><<<1024, 256>>>(partp, 8192, b1, g1, be1, c1h, c1l);
    // conv2: split-K 8 -> partials -> combine (+res, float out)
    gconv_mma<128, 8><<<dim3(32, 8), 256, SMEM>>>(
        c1h, c1l, knn2p, w2h, w2l, partp, 4096, 2048, 4096);
    combine_final<8><<<512, 256>>>(
        partp, 4096, b2, g2, be2, res1p, out + 2 * 2048 * 3, 2048);
    // pos output
    poscopy_kernel<<<48, 256>>>(pos, out);
}

// round 7
// speedup vs baseline: 1.0133x; 1.0133x over previous
#include <cuda_runtime.h>
#include <cstdint>
#include <cstddef>
#include <math.h>

// ---------------------------------------------------------------------------
// Scratch (device globals -- no allocation allowed)
// ---------------------------------------------------------------------------
__device__ int   g_knn1[2 * 4096 * 16];
__device__ int   g_knn2[2 * 2048 * 16];
__device__ float g_res1[2 * 4096 * 128];
__device__ float g_part[4194304];          // split-K partials (16MB)
__device__ uint4 g_W1p[65536];             // W1 fragment-permuted (1MB)
__device__ uint4 g_W2p[131072];            // W2 fragment-permuted (2MB)
__device__ uint2 g_chp[1048576];           // ch  interleaved tf32 hi/lo (8MB)
__device__ uint2 g_ch1p[1048576];          // ch1 interleaved tf32 hi/lo (8MB)

// ---------------------------------------------------------------------------
// helpers
// ---------------------------------------------------------------------------
__device__ __forceinline__ unsigned int to_tf32(float v) {
    unsigned int r;
    asm("cvt.rna.tf32.f32 %0, %1;" : "=r"(r) : "f"(v));
    return r;
}
__device__ __forceinline__ void split_tf32(float v, unsigned int& hi,
                                           unsigned int& lo) {
    hi = to_tf32(v);
    lo = to_tf32(v - __uint_as_float(hi));
}
__device__ __forceinline__ void mma_tf32(float c[4], const unsigned int a[4],
                                         unsigned int b0, unsigned int b1) {
    asm("mma.sync.aligned.m16n8k8.row.col.f32.tf32.tf32.f32 "
        "{%0,%1,%2,%3}, {%4,%5,%6,%7}, {%8,%9}, {%0,%1,%2,%3};"
        : "+f"(c[0]), "+f"(c[1]), "+f"(c[2]), "+f"(c[3])
        : "r"(a[0]), "r"(a[1]), "r"(a[2]), "r"(a[3]), "r"(b0), "r"(b1));
}
__device__ __forceinline__ unsigned long long pack2(float x, float y) {
    unsigned long long r;
    asm("mov.b64 %0, {%1, %2};" : "=l"(r) : "f"(x), "f"(y));
    return r;
}
__device__ __forceinline__ unsigned long long add2(unsigned long long a,
                                                   unsigned long long b) {
    unsigned long long r;
    asm("add.rn.f32x2 %0, %1, %2;" : "=l"(r) : "l"(a), "l"(b));
    return r;
}
__device__ __forceinline__ unsigned long long mul2(unsigned long long a,
                                                   unsigned long long b) {
    unsigned long long r;
    asm("mul.rn.f32x2 %0, %1, %2;" : "=l"(r) : "l"(a), "l"(b));
    return r;
}

// ---------------------------------------------------------------------------
// prep: W1/W2 -> fragment-permuted uint4 planes; ch -> interleaved uint2.
// Wp[p][n][t] = {hi(W[n][8p+t]), hi(W[n][8p+t+4]),
//                lo(W[n][8p+t]), lo(W[n][8p+t+4])}
// ---------------------------------------------------------------------------
__global__ void __launch_bounds__(256) split_kernel(
    const float* __restrict__ W1, const float* __restrict__ W2,
    const float* __restrict__ ch)
{
    int i = blockIdx.x * 256 + threadIdx.x;
    if (i < 65536) {                               // W1p
        int p = i >> 9, n = (i >> 2) & 127, t = i & 3;
        int k0 = 8 * p + t;
        float v0 = __ldg(W1 + n * 1024 + k0);
        float v1 = __ldg(W1 + n * 1024 + k0 + 4);
        uint4 o;
        split_tf32(v0, o.x, o.z);
        split_tf32(v1, o.y, o.w);
        g_W1p[i] = o;
    } else if (i < 65536 + 131072) {               // W2p
        int j = i - 65536;
        int p = j >> 9, n = (j >> 2) & 127, t = j & 3;
        int k0 = 8 * p + t;
        float v0 = __ldg(W2 + n * 2048 + k0);
        float v1 = __ldg(W2 + n * 2048 + k0 + 4);
        uint4 o;
        split_tf32(v0, o.x, o.z);
        split_tf32(v1, o.y, o.w);
        g_W2p[j] = o;
    } else if (i < 65536 + 131072 + 262144) {      // chp (4 floats/thread)
        int j = i - 196608;
        float4 v = __ldg((const float4*)ch + j);
        uint4 s0, s1;
        split_tf32(v.x, s0.x, s0.y);
        split_tf32(v.y, s0.z, s0.w);
        split_tf32(v.z, s1.x, s1.y);
        split_tf32(v.w, s1.z, s1.w);
        ((uint4*)g_chp)[2 * j]     = s0;
        ((uint4*)g_chp)[2 * j + 1] = s1;
    }
}

// ---------------------------------------------------------------------------
// KNN: both stages in one launch. Warp-per-center, negated-SoA smem tiles,
// packed f32x2 distance math (rounds exactly like scalar rn ops).
// Lanes 0..15 hold sorted top-16 u64 keys ((dist_bits<<32)|idx); reproduces
// jax.lax.top_k(-d2) ordering (d asc, idx asc) exactly.
// ---------------------------------------------------------------------------
__global__ void __launch_bounds__(256) knn_kernel(
    const float* __restrict__ pos, int* __restrict__ knn1,
    int* __restrict__ knn2)
{
    constexpr int TILE = 1024;
    __shared__ __align__(16) float sn[3 * TILE];

    const int tid  = threadIdx.x;
    const int warp = tid >> 5;
    const int lane = tid & 31;

    int pstride, n_in, n_out, center;
    int* outp;
    if (blockIdx.x < 1024) {
        pstride = 1; n_in = 8192; n_out = 4096; outp = knn1;
        center = blockIdx.x * 8 + warp;
    } else {
        pstride = 2; n_in = 4096; n_out = 2048; outp = knn2;
        center = (blockIdx.x - 1024) * 8 + warp;
    }
    const int b = center / n_out;
    const int n = center % n_out;

    const float* posb = pos + (size_t)b * 8192 * 3;
    const float cx = posb[(size_t)(n * 2 * pstride) * 3 + 0];
    const float cy = posb[(size_t)(n * 2 * pstride) * 3 + 1];
    const float cz = posb[(size_t)(n * 2 * pstride) * 3 + 2];
    const unsigned long long cxx = pack2(cx, cx);
    const unsigned long long cyy = pack2(cy, cy);
    const unsigned long long czz = pack2(cz, cz);

    unsigned long long lkey   = 0x7F800000FFFFFFFFull;
    unsigned long long thresh = 0x7F800000FFFFFFFFull;
    float tf = __int_as_float(0x7F800000);

    const int nTiles = n_in / TILE;
    float v[12];

#pragma unroll
    for (int k = 0; k < 4; k++) {
        int p = k * 256 + tid;
#pragma unroll
        for (int d = 0; d < 3; d++)
            v[3 * k + d] = __ldg(posb + (size_t)p * pstride * 3 + d);
    }

    for (int t = 0; t < nTiles; t++) {
#pragma unroll
        for (int k = 0; k < 4; k++) {
            int p = k * 256 + tid;
            sn[p]        = -v[3 * k];
            sn[p + 1024] = -v[3 * k + 1];
            sn[p + 2048] = -v[3 * k + 2];
        }
        __syncthreads();
        if (t + 1 < nTiles) {
            const int base = (t + 1) * TILE;
#pragma unroll
            for (int k = 0; k < 4; k++) {
                int p = base + k * 256 + tid;
#pragma unroll
                for (int d = 0; d < 3; d++)
                    v[3 * k + d] = __ldg(posb + (size_t)p * pstride * 3 + d);
            }
        }

        const int jbase = t * TILE;
#pragma unroll 4
        for (int it = 0; it < 16; ++it) {
            const int j = it * 64 + 2 * lane;
            unsigned long long nx = *(const unsigned long long*)(sn + j);
            unsigned long long ny = *(const unsigned long long*)(sn + 1024 + j);
            unsigned long long nz = *(const unsigned long long*)(sn + 2048 + j);
            unsigned long long ax = add2(cxx, nx);
            unsigned long long ay = add2(cyy, ny);
            unsigned long long az = add2(czz, nz);
            unsigned long long dp =
                add2(add2(mul2(ax, ax), mul2(ay, ay)), mul2(az, az));
            float d0, d1;
            asm("mov.b64 {%0, %1}, %2;" : "=f"(d0), "=f"(d1) : "l"(dp));
#pragma unroll
            for (int h = 0; h < 2; h++) {
                float dv = h ? d1 : d0;
                unsigned mask = __ballot_sync(0xffffffffu, dv <= tf);
                while (mask) {
                    const int src = __ffs(mask) - 1;
                    mask &= mask - 1;
                    float cd = __shfl_sync(0xffffffffu, dv, src);
                    unsigned idx = (unsigned)(jbase + it * 64 + 2 * src + h);
                    unsigned long long ck =
                        ((unsigned long long)__float_as_uint(cd) << 32) | idx;
                    if (ck < thresh) {
                        unsigned long long up =
                            __shfl_up_sync(0xffffffffu, lkey, 1);
                        bool keep = (lkey < ck);
                        unsigned long long ins =
                            (lane == 0 || up < ck) ? ck : up;
                        lkey = keep ? lkey : ins;
                        thresh = __shfl_sync(0xffffffffu, lkey, 15);
                        tf = __uint_as_float((unsigned)(thresh >> 32));
                    }
                }
            }
        }
        __syncthreads();
    }

    if (lane < 16)
        outp[(size_t)center * 16 + lane] =
            (int)(unsigned)(lkey & 0xffffffffull);
}

// ---------------------------------------------------------------------------
// Gathered-conv GEMM, 3xTF32 tensor cores. A: gathered interleaved-hi/lo
// uint2 smem (stride 132 -> conflict-free LDS.64). B: fragment-permuted W
// read directly from global as one LDG.128 per fragment (L1-resident).
// 256 threads, BM=128 x BN=128, 8 warps (4M x 2N), split-K over neighbors.
// ---------------------------------------------------------------------------
template <int CIN, int NSPLIT>
__global__ void __launch_bounds__(256, 2)
gconv_mma(const uint2* __restrict__ chp, const int* __restrict__ knn,
          const uint4* __restrict__ Wp, float* __restrict__ part,
          int n_in, int n_out, int Mtot)
{
    constexpr int BM = 128, BN = 128, BK = 16, S2 = 132;
    constexpr int PLANE = BK * S2;           // uint2 units
    constexpr int NPB = 16 / NSPLIT;
    constexpr int ITERS = NPB * CIN / BK;
    __shared__ __align__(16) uint2 sm[2 * PLANE];   // 33792 bytes

    const int tid = threadIdx.x;
    const int split = blockIdx.y;
    const int m_base = blockIdx.x * BM;
    const int b = m_base / n_out;
    const int warp = tid >> 5, lane = tid & 31;
    const int g = lane >> 2, t = lane & 3;
    const int wm = (warp & 3) * 32, wn = (warp >> 2) * 64;

    const int arow = tid >> 1;
    const int aoff = (tid & 1) * 8;
    const int* knnrow = knn + (size_t)(m_base + arow) * 16;
    const uint2* chb = chp + (size_t)b * n_in * CIN;
    const int kbase = split * NPB * CIN;     // first k of this split

    float acc[2][8][4];
#pragma unroll
    for (int i = 0; i < 2; i++)
#pragma unroll
        for (int j = 0; j < 8; j++)
#pragma unroll
            for (int k = 0; k < 4; k++) acc[i][j][k] = 0.0f;

    uint4 ra[4];                             // 8 uint2 = 4 uint4

    auto loadA = [&](int it) {
        const int kn = split * NPB + (it * BK) / CIN;
        const int c0 = (it * BK) % CIN;
        const int j = __ldg(&knnrow[kn]);
        const uint4* src = (const uint4*)(chb + (size_t)j * CIN + c0 + aoff);
#pragma unroll
        for (int q = 0; q < 4; q++) ra[q] = __ldg(src + q);
    };
    auto storeA = [&](int buf) {
        uint2* dst = sm + buf * PLANE + aoff * S2 + arow;
#pragma unroll
        for (int q = 0; q < 4; q++) {
            dst[(2 * q) * S2]     = make_uint2(ra[q].x, ra[q].y);
            dst[(2 * q + 1) * S2] = make_uint2(ra[q].z, ra[q].w);
        }
    };

    loadA(0); storeA(0);
    __syncthreads();
    int cur = 0;

    for (int it = 0; it < ITERS; ++it) {
        if (it + 1 < ITERS) loadA(it + 1);
        const uint2* As = sm + cur * PLANE;
#pragma unroll
        for (int k0 = 0; k0 < BK; k0 += 8) {
            // A fragments: 8 LDS.64, conflict-free
            unsigned int Abf[2][4], Alf[2][4];
#pragma unroll
            for (int mt = 0; mt < 2; mt++) {
                const int r0 = wm + mt * 16 + g;
                uint2 a0 = As[(k0 + t) * S2 + r0];
                uint2 a1 = As[(k0 + t) * S2 + r0 + 8];
                uint2 a2 = As[(k0 + t + 4) * S2 + r0];
                uint2 a3 = As[(k0 + t + 4) * S2 + r0 + 8];
                Abf[mt][0] = a0.x; Alf[mt][0] = a0.y;
                Abf[mt][1] = a1.x; Alf[mt][1] = a1.y;
                Abf[mt][2] = a2.x; Alf[mt][2] = a2.y;
                Abf[mt][3] = a3.x; Alf[mt][3] = a3.y;
            }
            // B fragments straight from permuted global (L1 hits)
            const int p = (kbase + it * BK + k0) >> 3;
            const uint4* wb = Wp + (((size_t)p << 7) << 2);  // p*128*4
#pragma unroll
            for (int nt = 0; nt < 8; nt++) {
                uint4 w = __ldg(wb + (((wn + nt * 8 + g) << 2) + t));
#pragma unroll
                for (int mt = 0; mt < 2; mt++) {
                    mma_tf32(acc[mt][nt], Abf[mt], w.x, w.y);
                    mma_tf32(acc[mt][nt], Abf[mt], w.z, w.w);
                    mma_tf32(acc[mt][nt], Alf[mt], w.x, w.y);
                }
            }
        }
        if (it + 1 < ITERS) {
            storeA(cur ^ 1);
            __syncthreads();
            cur ^= 1;
        }
    }

    float* dst = part + ((size_t)split * Mtot + m_base) * BN;
#pragma unroll
    for (int mt = 0; mt < 2; mt++)
#pragma unroll
        for (int nt = 0; nt < 8; nt++) {
            const int r = wm + mt * 16 + g;
            const int c = wn + nt * 8 + 2 * t;
            *(float2*)(dst + (size_t)r * BN + c) =
                make_float2(acc[mt][nt][0], acc[mt][nt][1]);
            *(float2*)(dst + (size_t)(r + 8) * BN + c) =
                make_float2(acc[mt][nt][2], acc[mt][nt][3]);
        }
}

// ---------------------------------------------------------------------------
// combine (mid): sum partials + bias + LN + SiLU -> interleaved tf32 uint2
// ---------------------------------------------------------------------------
template <int NSPLIT>
__global__ void __launch_bounds__(256) combine_mid(
    const float* __restrict__ part, int M,
    const float* __restrict__ bias, const float* __restrict__ gamma,
    const float* __restrict__ beta, uint2* __restrict__ outp)
{
    const int lane = threadIdx.x & 31;
    const int row = blockIdx.x * 8 + (threadIdx.x >> 5);

    const float4* p4 = (const float4*)part;
    float4 x = p4[(size_t)row * 32 + lane];
#pragma unroll
    for (int s = 1; s < NSPLIT; s++) {
        float4 y = p4[((size_t)s * M + row) * 32 + lane];
        x.x += y.x; x.y += y.y; x.z += y.z; x.w += y.w;
    }
    float4 bb = *(const float4*)(bias + lane * 4);
    float4 gg = *(const float4*)(gamma + lane * 4);
    float4 be = *(const float4*)(beta + lane * 4);
    x.x += bb.x; x.y += bb.y; x.z += bb.z; x.w += bb.w;

    float s = x.x + x.y + x.z + x.w;
#pragma unroll
    for (int off = 16; off; off >>= 1) s += __shfl_xor_sync(~0u, s, off);
    float mu = s * (1.0f / 128.0f);
    float d0 = x.x - mu, d1 = x.y - mu, d2 = x.z - mu, d3 = x.w - mu;
    float s2 = d0 * d0 + d1 * d1 + d2 * d2 + d3 * d3;
#pragma unroll
    for (int off = 16; off; off >>= 1) s2 += __shfl_xor_sync(~0u, s2, off);
    float rstd = rsqrtf(s2 * (1.0f / 128.0f) + 1e-5f);

    float y0 = d0 * rstd * gg.x + be.x;
    float y1 = d1 * rstd * gg.y + be.y;
    float y2 = d2 * rstd * gg.z + be.z;
    float y3 = d3 * rstd * gg.w + be.w;
    y0 = y0 / (1.0f + expf(-y0));
    y1 = y1 / (1.0f + expf(-y1));
    y2 = y2 / (1.0f + expf(-y2));
    y3 = y3 / (1.0f + expf(-y3));

    uint4 s0, s1;
    split_tf32(y0, s0.x, s0.y);
    split_tf32(y1, s0.z, s0.w);
    split_tf32(y2, s1.x, s1.y);
    split_tf32(y3, s1.z, s1.w);
    ((uint4*)outp)[(size_t)row * 64 + lane * 2]     = s0;
    ((uint4*)outp)[(size_t)row * 64 + lane * 2 + 1] = s1;
}

// ---------------------------------------------------------------------------
// combine (final): sum partials + bias + LN + SiLU + residual -> float out
// ---------------------------------------------------------------------------
template <int NSPLIT>
__global__ void __launch_bounds__(256) combine_final(
    const float* __restrict__ part, int M,
    const float* __restrict__ bias, const float* __restrict__ gamma,
    const float* __restrict__ beta, const float* __restrict__ res_in,
    float* __restrict__ out, int n_out)
{
    const int lane = threadIdx.x & 31;
    const int row = blockIdx.x * 8 + (threadIdx.x >> 5);

    const float4* p4 = (const float4*)part;
    float4 x = p4[(size_t)row * 32 + lane];
#pragma unroll
    for (int s = 1; s < NSPLIT; s++) {
        float4 y = p4[((size_t)s * M + row) * 32 + lane];
        x.x += y.x; x.y += y.y; x.z += y.z; x.w += y.w;
    }
    float4 bb = *(const float4*)(bias + lane * 4);
    float4 gg = *(const float4*)(gamma + lane * 4);
    float4 be = *(const float4*)(beta + lane * 4);
    x.x += bb.x; x.y += bb.y; x.z += bb.z; x.w += bb.w;

    float s = x.x + x.y + x.z + x.w;
#pragma unroll
    for (int off = 16; off; off >>= 1) s += __shfl_xor_sync(~0u, s, off);
    float mu = s * (1.0f / 128.0f);
    float d0 = x.x - mu, d1 = x.y - mu, d2 = x.z - mu, d3 = x.w - mu;
    float s2 = d0 * d0 + d1 * d1 + d2 * d2 + d3 * d3;
#pragma unroll
    for (int off = 16; off; off >>= 1) s2 += __shfl_xor_sync(~0u, s2, off);
    float rstd = rsqrtf(s2 * (1.0f / 128.0f) + 1e-5f);

    float y0 = d0 * rstd * gg.x + be.x;
    float y1 = d1 * rstd * gg.y + be.y;
    float y2 = d2 * rstd * gg.z + be.z;
    float y3 = d3 * rstd * gg.w + be.w;
    float4 o4;
    o4.x = y0 / (1.0f + expf(-y0));
    o4.y = y1 / (1.0f + expf(-y1));
    o4.z = y2 / (1.0f + expf(-y2));
    o4.w = y3 / (1.0f + expf(-y3));

    const int b2 = row / n_out;
    const int nn = row % n_out;
    const float4 rr = *(const float4*)(
        res_in + ((size_t)b2 * (2 * n_out) + 2 * nn) * 128 + lane * 4);
    o4.x += rr.x; o4.y += rr.y; o4.z += rr.z; o4.w += rr.w;
    ((float4*)out)[(size_t)row * 32 + lane] = o4;
}

// ---------------------------------------------------------------------------
// Residual path (stage 1): res1[b,n,:] = ch[b,2n,:] @ Wres + bres
// ---------------------------------------------------------------------------
__global__ void __launch_bounds__(128) res_kernel(
    const float* __restrict__ ch, const float* __restrict__ Wres,
    const float* __restrict__ bres, float* __restrict__ res1)
{
    __shared__ float s_w[64 * 128];
    __shared__ float s_ch[8][64];
    const int tid = threadIdx.x;
    const int m_base = blockIdx.x * 64;
    const int b = m_base / 4096;
    const int n_base = m_base % 4096;

    for (int i = tid; i < 64 * 128 / 4; i += 128)
        ((float4*)s_w)[i] = ((const float4*)Wres)[i];
    __syncthreads();

    const float bias = __ldg(&bres[tid]);
    const int rr = tid >> 4, q = tid & 15;

    for (int g = 0; g < 8; g++) {
        const float* src = ch +
            ((size_t)b * 8192 + 2 * (n_base + g * 8 + rr)) * 64 + q * 4;
        *(float4*)&s_ch[rr][q * 4] = *(const float4*)src;
        __syncthreads();
        float acc[8];
#pragma unroll
        for (int t = 0; t < 8; t++) acc[t] = bias;
        for (int c = 0; c < 64; c++) {
            float wv = s_w[c * 128 + tid];
#pragma unroll
            for (int t = 0; t < 8; t++) acc[t] += s_ch[t][c] * wv;
        }
#pragma unroll
        for (int t = 0; t < 8; t++)
            res1[(size_t)(m_base + g * 8 + t) * 128 + tid] = acc[t];
        __syncthreads();
    }
}

// ---------------------------------------------------------------------------
__global__ void poscopy_kernel(const float* __restrict__ pos,
                               float* __restrict__ out)
{
    int i = blockIdx.x * blockDim.x + threadIdx.x;
    if (i < 2 * 2048 * 3) {
        int b = i / 6144;
        int rem = i - b * 6144;
        int n = rem / 3;
        int d = rem - n * 3;
        out[i] = pos[((size_t)b * 8192 + 4 * n) * 3 + d];
    }
}

// ---------------------------------------------------------------------------
extern "C" void kernel_launch(void* const* d_in, const int* in_sizes, int n_in,
                              void* d_out, int out_size)
{
    const float* pos  = (const float*)d_in[0];
    const float* ch   = (const float*)d_in[1];
    const float* W1   = (const float*)d_in[2];
    const float* b1   = (const float*)d_in[3];
    const float* Wres = (const float*)d_in[4];
    const float* bres = (const float*)d_in[5];
    const float* W2   = (const float*)d_in[6];
    const float* b2   = (const float*)d_in[7];
    const float* g1   = (const float*)d_in[8];
    const float* be1  = (const float*)d_in[9];
    const float* g2   = (const float*)d_in[10];
    const float* be2  = (const float*)d_in[11];
    float* out = (float*)d_out;

    int *knn1p, *knn2p;
    float *res1p, *partp;
    uint4 *w1p, *w2p;
    uint2 *chp, *c1p;
    cudaGetSymbolAddress((void**)&knn1p, g_knn1);
    cudaGetSymbolAddress((void**)&knn2p, g_knn2);
    cudaGetSymbolAddress((void**)&res1p, g_res1);
    cudaGetSymbolAddress((void**)&partp, g_part);
    cudaGetSymbolAddress((void**)&w1p, g_W1p);
    cudaGetSymbolAddress((void**)&w2p, g_W2p);
    cudaGetSymbolAddress((void**)&chp, g_chp);
    cudaGetSymbolAddress((void**)&c1p, g_ch1p);

    // prep: permuted/split planes (65536 + 131072 + 262144 items)
    split_kernel<<<1792, 256>>>(W1, W2, ch);
    // KNN (both stages, one launch)
    knn_kernel<<<1536, 256>>>(pos, knn1p, knn2p);
    // residual GEMM (stage 1)
    res_kernel<<<128, 128>>>(ch, Wres, bres, res1p);
    // conv1: split-K 4 -> partials -> combine (writes ch1 interleaved)
    gconv_mma<64, 4><<<dim3(64, 4), 256>>>(
        chp, knn1p, w1p, partp, 8192, 4096, 8192);
    combine_mid<4><<<1024, 256>>>(partp, 8192, b1, g1, be1, c1p);
    // conv2: split-K 8 -> partials -> combine (+res, float out)
    gconv_mma<128, 8><<<dim3(32, 8), 256>>>(
        c1p, knn2p, w2p, partp, 4096, 2048, 4096);
    combine_final<8><<<512, 256>>>(
        partp, 4096, b2, g2, be2, res1p, out + 2 * 2048 * 3, 2048);
    // pos output
    poscopy_kernel<<<48, 256>>>(pos, out);
}

// round 8
// speedup vs baseline: 1.0866x; 1.0724x over previous
#include <cuda_runtime.h>
#include <cstdint>
#include <cstddef>
#include <math.h>

// ---------------------------------------------------------------------------
// Scratch (device globals -- no allocation allowed)
// ---------------------------------------------------------------------------
__device__ int   g_knn1[2 * 4096 * 16];
__device__ int   g_knn2[2 * 2048 * 16];
__device__ float g_res1[2 * 4096 * 128];
__device__ float g_part[4194304];          // split-K partials (16MB)
__device__ uint4 g_W1p[65536];             // W1 fragment-permuted (1MB)
__device__ uint4 g_W2p[131072];            // W2 fragment-permuted (2MB)
__device__ uint2 g_chp[1048576];           // ch  interleaved tf32 hi/lo (8MB)
__device__ uint2 g_ch1p[1048576];          // ch1 interleaved tf32 hi/lo (8MB)

// ---------------------------------------------------------------------------
// helpers
// ---------------------------------------------------------------------------
__device__ __forceinline__ unsigned int to_tf32(float v) {
    unsigned int r;
    asm("cvt.rna.tf32.f32 %0, %1;" : "=r"(r) : "f"(v));
    return r;
}
__device__ __forceinline__ void split_tf32(float v, unsigned int& hi,
                                           unsigned int& lo) {
    hi = to_tf32(v);
    lo = to_tf32(v - __uint_as_float(hi));
}
__device__ __forceinline__ void mma_tf32(float c[4], const unsigned int a[4],
                                         unsigned int b0, unsigned int b1) {
    asm("mma.sync.aligned.m16n8k8.row.col.f32.tf32.tf32.f32 "
        "{%0,%1,%2,%3}, {%4,%5,%6,%7}, {%8,%9}, {%0,%1,%2,%3};"
        : "+f"(c[0]), "+f"(c[1]), "+f"(c[2]), "+f"(c[3])
        : "r"(a[0]), "r"(a[1]), "r"(a[2]), "r"(a[3]), "r"(b0), "r"(b1));
}
__device__ __forceinline__ unsigned long long pack2(float x, float y) {
    unsigned long long r;
    asm("mov.b64 %0, {%1, %2};" : "=l"(r) : "f"(x), "f"(y));
    return r;
}
__device__ __forceinline__ unsigned long long add2(unsigned long long a,
                                                   unsigned long long b) {
    unsigned long long r;
    asm("add.rn.f32x2 %0, %1, %2;" : "=l"(r) : "l"(a), "l"(b));
    return r;
}
__device__ __forceinline__ unsigned long long mul2(unsigned long long a,
                                                   unsigned long long b) {
    unsigned long long r;
    asm("mul.rn.f32x2 %0, %1, %2;" : "=l"(r) : "l"(a), "l"(b));
    return r;
}
__device__ __forceinline__ void cp_async8(unsigned int dst, const void* src) {
    asm volatile("cp.async.ca.shared.global [%0], [%1], 8;"
                 :: "r"(dst), "l"(src));
}
__device__ __forceinline__ void cp_async16(unsigned int dst, const void* src) {
    asm volatile("cp.async.cg.shared.global [%0], [%1], 16;"
                 :: "r"(dst), "l"(src));
}

// ---------------------------------------------------------------------------
// prep: W1/W2 -> fragment-permuted uint4 planes; ch -> interleaved uint2.
// Wp[p][n][t] = {hi(W[n][8p+t]), hi(W[n][8p+t+4]),
//                lo(W[n][8p+t]), lo(W[n][8p+t+4])}
// ---------------------------------------------------------------------------
__global__ void __launch_bounds__(256) split_kernel(
    const float* __restrict__ W1, const float* __restrict__ W2,
    const float* __restrict__ ch)
{
    int i = blockIdx.x * 256 + threadIdx.x;
    if (i < 65536) {                               // W1p
        int p = i >> 9, n = (i >> 2) & 127, t = i & 3;
        int k0 = 8 * p + t;
        float v0 = __ldg(W1 + n * 1024 + k0);
        float v1 = __ldg(W1 + n * 1024 + k0 + 4);
        uint4 o;
        split_tf32(v0, o.x, o.z);
        split_tf32(v1, o.y, o.w);
        g_W1p[i] = o;
    } else if (i < 65536 + 131072) {               // W2p
        int j = i - 65536;
        int p = j >> 9, n = (j >> 2) & 127, t = j & 3;
        int k0 = 8 * p + t;
        float v0 = __ldg(W2 + n * 2048 + k0);
        float v1 = __ldg(W2 + n * 2048 + k0 + 4);
        uint4 o;
        split_tf32(v0, o.x, o.z);
        split_tf32(v1, o.y, o.w);
        g_W2p[j] = o;
    } else if (i < 65536 + 131072 + 262144) {      // chp (4 floats/thread)
        int j = i - 196608;
        float4 v = __ldg((const float4*)ch + j);
        uint4 s0, s1;
        split_tf32(v.x, s0.x, s0.y);
        split_tf32(v.y, s0.z, s0.w);
        split_tf32(v.z, s1.x, s1.y);
        split_tf32(v.w, s1.z, s1.w);
        ((uint4*)g_chp)[2 * j]     = s0;
        ((uint4*)g_chp)[2 * j + 1] = s1;
    }
}

// ---------------------------------------------------------------------------
// KNN: both stages in one launch. Warp-per-center, negated-SoA smem tiles,
// packed f32x2 distance math (rounds exactly like scalar rn ops).
// Lanes 0..15 hold sorted top-16 u64 keys ((dist_bits<<32)|idx); reproduces
// jax.lax.top_k(-d2) ordering (d asc, idx asc) exactly.
// ---------------------------------------------------------------------------
__global__ void __launch_bounds__(256) knn_kernel(
    const float* __restrict__ pos, int* __restrict__ knn1,
    int* __restrict__ knn2)
{
    constexpr int TILE = 1024;
    __shared__ __align__(16) float sn[3 * TILE];

    const int tid  = threadIdx.x;
    const int warp = tid >> 5;
    const int lane = tid & 31;

    int pstride, n_in, n_out, center;
    int* outp;
    if (blockIdx.x < 1024) {
        pstride = 1; n_in = 8192; n_out = 4096; outp = knn1;
        center = blockIdx.x * 8 + warp;
    } else {
        pstride = 2; n_in = 4096; n_out = 2048; outp = knn2;
        center = (blockIdx.x - 1024) * 8 + warp;
    }
    const int b = center / n_out;
    const int n = center % n_out;

    const float* posb = pos + (size_t)b * 8192 * 3;
    const float cx = posb[(size_t)(n * 2 * pstride) * 3 + 0];
    const float cy = posb[(size_t)(n * 2 * pstride) * 3 + 1];
    const float cz = posb[(size_t)(n * 2 * pstride) * 3 + 2];
    const unsigned long long cxx = pack2(cx, cx);
    const unsigned long long cyy = pack2(cy, cy);
    const unsigned long long czz = pack2(cz, cz);

    unsigned long long lkey   = 0x7F800000FFFFFFFFull;
    unsigned long long thresh = 0x7F800000FFFFFFFFull;
    float tf = __int_as_float(0x7F800000);

    const int nTiles = n_in / TILE;
    float v[12];

#pragma unroll
    for (int k = 0; k < 4; k++) {
        int p = k * 256 + tid;
#pragma unroll
        for (int d = 0; d < 3; d++)
            v[3 * k + d] = __ldg(posb + (size_t)p * pstride * 3 + d);
    }

    for (int t = 0; t < nTiles; t++) {
#pragma unroll
        for (int k = 0; k < 4; k++) {
            int p = k * 256 + tid;
            sn[p]        = -v[3 * k];
            sn[p + 1024] = -v[3 * k + 1];
            sn[p + 2048] = -v[3 * k + 2];
        }
        __syncthreads();
        if (t + 1 < nTiles) {
            const int base = (t + 1) * TILE;
#pragma unroll
            for (int k = 0; k < 4; k++) {
                int p = base + k * 256 + tid;
#pragma unroll
                for (int d = 0; d < 3; d++)
                    v[3 * k + d] = __ldg(posb + (size_t)p * pstride * 3 + d);
            }
        }

        const int jbase = t * TILE;
#pragma unroll 4
        for (int it = 0; it < 16; ++it) {
            const int j = it * 64 + 2 * lane;
            unsigned long long nx = *(const unsigned long long*)(sn + j);
            unsigned long long ny = *(const unsigned long long*)(sn + 1024 + j);
            unsigned long long nz = *(const unsigned long long*)(sn + 2048 + j);
            unsigned long long ax = add2(cxx, nx);
            unsigned long long ay = add2(cyy, ny);
            unsigned long long az = add2(czz, nz);
            unsigned long long dp =
                add2(add2(mul2(ax, ax), mul2(ay, ay)), mul2(az, az));
            float d0, d1;
            asm("mov.b64 {%0, %1}, %2;" : "=f"(d0), "=f"(d1) : "l"(dp));
#pragma unroll
            for (int h = 0; h < 2; h++) {
                float dv = h ? d1 : d0;
                unsigned mask = __ballot_sync(0xffffffffu, dv <= tf);
                while (mask) {
                    const int src = __ffs(mask) - 1;
                    mask &= mask - 1;
                    float cd = __shfl_sync(0xffffffffu, dv, src);
                    unsigned idx = (unsigned)(jbase + it * 64 + 2 * src + h);
                    unsigned long long ck =
                        ((unsigned long long)__float_as_uint(cd) << 32) | idx;
                    if (ck < thresh) {
                        unsigned long long up =
                            __shfl_up_sync(0xffffffffu, lkey, 1);
                        bool keep = (lkey < ck);
                        unsigned long long ins =
                            (lane == 0 || up < ck) ? ck : up;
                        lkey = keep ? lkey : ins;
                        thresh = __shfl_sync(0xffffffffu, lkey, 15);
                        tf = __uint_as_float((unsigned)(thresh >> 32));
                    }
                }
            }
        }
        __syncthreads();
    }

    if (lane < 16)
        outp[(size_t)center * 16 + lane] =
            (int)(unsigned)(lkey & 0xffffffffull);
}

// ---------------------------------------------------------------------------
// Gathered-conv GEMM, 3xTF32 tensor cores.
// A: cp.async(8B) gathered into interleaved hi/lo uint2 smem (stride 132,
//    conflict-free LDS.64 fragments).
// B: cp.async(16B) of the fragment-permuted W image into smem; each consumer
//    fragment is ONE conflict-free LDS.128.
// 256 threads, BM=128 x BN=128, 8 warps (4M x 2N), split-K over neighbors,
// double-buffered via cp.async groups.
// ---------------------------------------------------------------------------
template <int CIN, int NSPLIT>
__global__ void __launch_bounds__(256, 2)
gconv_mma(const uint2* __restrict__ chp, const int* __restrict__ knn,
          const uint4* __restrict__ Wp, float* __restrict__ part,
          int n_in, int n_out, int Mtot)
{
    constexpr int BM = 128, BN = 128, BK = 16, S2 = 132;
    constexpr int APLANE = BK * S2;          // uint2 units (2112)
    constexpr int BPLANE = 1024;             // uint4 units per k-tile
    constexpr int NPB = 16 / NSPLIT;
    constexpr int ITERS = NPB * CIN / BK;
    extern __shared__ __align__(16) unsigned char dynraw[];
    uint2* As2 = (uint2*)dynraw;                          // 2*APLANE uint2
    uint4* Bs4 = (uint4*)(dynraw + 2 * APLANE * 8);       // 2*BPLANE uint4

    const int tid = threadIdx.x;
    const int split = blockIdx.y;
    const int m_base = blockIdx.x * BM;
    const int b = m_base / n_out;
    const int warp = tid >> 5, lane = tid & 31;
    const int g = lane >> 2, t = lane & 3;
    const int wm = (warp & 3) * 32, wn = (warp >> 2) * 64;

    const int arow = tid >> 1;
    const int aoff = (tid & 1) * 8;
    const int* knnrow = knn + (size_t)(m_base + arow) * 16;
    const uint2* chb = chp + (size_t)b * n_in * CIN;
    const int kpan0 = (split * NPB * CIN) >> 3;   // starting 8-wide k panel

    const unsigned int abase =
        (unsigned int)__cvta_generic_to_shared(As2) + (aoff * S2 + arow) * 8;
    const unsigned int bbase =
        (unsigned int)__cvta_generic_to_shared(Bs4) + tid * 4 * 16;

    float acc[2][8][4];
#pragma unroll
    for (int i = 0; i < 2; i++)
#pragma unroll
        for (int j = 0; j < 8; j++)
#pragma unroll
            for (int k = 0; k < 4; k++) acc[i][j][k] = 0.0f;

    auto issue = [&](int it, int buf) {
        const int kn = split * NPB + (it * BK) / CIN;
        const int c0 = (it * BK) % CIN;
        const int j = __ldg(&knnrow[kn]);
        const uint2* srcA = chb + (size_t)j * CIN + c0 + aoff;
        const unsigned int dA = abase + buf * (APLANE * 8);
#pragma unroll
        for (int i = 0; i < 8; i++) cp_async8(dA + i * (S2 * 8), srcA + i);
        const uint4* srcB = Wp + ((size_t)(kpan0 + it * 2) << 9) + tid * 4;
        const unsigned int dB = bbase + buf * (BPLANE * 16);
#pragma unroll
        for (int q = 0; q < 4; q++) cp_async16(dB + q * 16, srcB + q);
        asm volatile("cp.async.commit_group;");
    };

    issue(0, 0);
    int cur = 0;

    for (int it = 0; it < ITERS; ++it) {
        if (it + 1 < ITERS) {
            issue(it + 1, cur ^ 1);
            asm volatile("cp.async.wait_group 1;");
        } else {
            asm volatile("cp.async.wait_group 0;");
        }
        __syncthreads();

        const uint2* As = As2 + cur * APLANE;
        const uint4* Bs = Bs4 + cur * BPLANE;
#pragma unroll
        for (int k0 = 0; k0 < BK; k0 += 8) {
            unsigned int Abf[2][4], Alf[2][4];
#pragma unroll
            for (int mt = 0; mt < 2; mt++) {
                const int r0 = wm + mt * 16 + g;
                uint2 a0 = As[(k0 + t) * S2 + r0];
                uint2 a1 = As[(k0 + t) * S2 + r0 + 8];
                uint2 a2 = As[(k0 + t + 4) * S2 + r0];
                uint2 a3 = As[(k0 + t + 4) * S2 + r0 + 8];
                Abf[mt][0] = a0.x; Alf[mt][0] = a0.y;
                Abf[mt][1] = a1.x; Alf[mt][1] = a1.y;
                Abf[mt][2] = a2.x; Alf[mt][2] = a2.y;
                Abf[mt][3] = a3.x; Alf[mt][3] = a3.y;
            }
            const uint4* bp = Bs + (k0 >> 3) * 512;
#pragma unroll
            for (int nt = 0; nt < 8; nt++) {
                uint4 w = bp[(wn + nt * 8 + g) * 4 + t];
#pragma unroll
                for (int mt = 0; mt < 2; mt++) {
                    mma_tf32(acc[mt][nt], Abf[mt], w.x, w.y);
                    mma_tf32(acc[mt][nt], Abf[mt], w.z, w.w);
                    mma_tf32(acc[mt][nt], Alf[mt], w.x, w.y);
                }
            }
        }
        if (it + 1 < ITERS) __syncthreads();   // protect cur^1 before refill
        cur ^= 1;
    }

    float* dst = part + ((size_t)split * Mtot + m_base) * BN;
#pragma unroll
    for (int mt = 0; mt < 2; mt++)
#pragma unroll
        for (int nt = 0; nt < 8; nt++) {
            const int r = wm + mt * 16 + g;
            const int c = wn + nt * 8 + 2 * t;
            *(float2*)(dst + (size_t)r * BN + c) =
                make_float2(acc[mt][nt][0], acc[mt][nt][1]);
            *(float2*)(dst + (size_t)(r + 8) * BN + c) =
                make_float2(acc[mt][nt][2], acc[mt][nt][3]);
        }
}

// ---------------------------------------------------------------------------
// combine (mid): sum partials + bias + LN + SiLU -> interleaved tf32 uint2
// ---------------------------------------------------------------------------
template <int NSPLIT>
__global__ void __launch_bounds__(256) combine_mid(
    const float* __restrict__ part, int M,
    const float* __restrict__ bias, const float* __restrict__ gamma,
    const float* __restrict__ beta, uint2* __restrict__ outp)
{
    const int lane = threadIdx.x & 31;
    const int row = blockIdx.x * 8 + (threadIdx.x >> 5);

    const float4* p4 = (const float4*)part;
    float4 x = p4[(size_t)row * 32 + lane];
#pragma unroll
    for (int s = 1; s < NSPLIT; s++) {
        float4 y = p4[((size_t)s * M + row) * 32 + lane];
        x.x += y.x; x.y += y.y; x.z += y.z; x.w += y.w;
    }
    float4 bb = *(const float4*)(bias + lane * 4);
    float4 gg = *(const float4*)(gamma + lane * 4);
    float4 be = *(const float4*)(beta + lane * 4);
    x.x += bb.x; x.y += bb.y; x.z += bb.z; x.w += bb.w;

    float s = x.x + x.y + x.z + x.w;
#pragma unroll
    for (int off = 16; off; off >>= 1) s += __shfl_xor_sync(~0u, s, off);
    float mu = s * (1.0f / 128.0f);
    float d0 = x.x - mu, d1 = x.y - mu, d2 = x.z - mu, d3 = x.w - mu;
    float s2 = d0 * d0 + d1 * d1 + d2 * d2 + d3 * d3;
#pragma unroll
    for (int off = 16; off; off >>= 1) s2 += __shfl_xor_sync(~0u, s2, off);
    float rstd = rsqrtf(s2 * (1.0f / 128.0f) + 1e-5f);

    float y0 = d0 * rstd * gg.x + be.x;
    float y1 = d1 * rstd * gg.y + be.y;
    float y2 = d2 * rstd * gg.z + be.z;
    float y3 = d3 * rstd * gg.w + be.w;
    y0 = y0 / (1.0f + expf(-y0));
    y1 = y1 / (1.0f + expf(-y1));
    y2 = y2 / (1.0f + expf(-y2));
    y3 = y3 / (1.0f + expf(-y3));

    uint4 s0, s1;
    split_tf32(y0, s0.x, s0.y);
    split_tf32(y1, s0.z, s0.w);
    split_tf32(y2, s1.x, s1.y);
    split_tf32(y3, s1.z, s1.w);
    ((uint4*)outp)[(size_t)row * 64 + lane * 2]     = s0;
    ((uint4*)outp)[(size_t)row * 64 + lane * 2 + 1] = s1;
}

// ---------------------------------------------------------------------------
// combine (final): sum partials + bias + LN + SiLU + residual -> float out
// ---------------------------------------------------------------------------
template <int NSPLIT>
__global__ void __launch_bounds__(256) combine_final(
    const float* __restrict__ part, int M,
    const float* __restrict__ bias, const float* __restrict__ gamma,
    const float* __restrict__ beta, const float* __restrict__ res_in,
    float* __restrict__ out, int n_out)
{
    const int lane = threadIdx.x & 31;
    const int row = blockIdx.x * 8 + (threadIdx.x >> 5);

    const float4* p4 = (const float4*)part;
    float4 x = p4[(size_t)row * 32 + lane];
#pragma unroll
    for (int s = 1; s < NSPLIT; s++) {
        float4 y = p4[((size_t)s * M + row) * 32 + lane];
        x.x += y.x; x.y += y.y; x.z += y.z; x.w += y.w;
    }
    float4 bb = *(const float4*)(bias + lane * 4);
    float4 gg = *(const float4*)(gamma + lane * 4);
    float4 be = *(const float4*)(beta + lane * 4);
    x.x += bb.x; x.y += bb.y; x.z += bb.z; x.w += bb.w;

    float s = x.x + x.y + x.z + x.w;
#pragma unroll
    for (int off = 16; off; off >>= 1) s += __shfl_xor_sync(~0u, s, off);
    float mu = s * (1.0f / 128.0f);
    float d0 = x.x - mu, d1 = x.y - mu, d2 = x.z - mu, d3 = x.w - mu;
    float s2 = d0 * d0 + d1 * d1 + d2 * d2 + d3 * d3;
#pragma unroll
    for (int off = 16; off; off >>= 1) s2 += __shfl_xor_sync(~0u, s2, off);
    float rstd = rsqrtf(s2 * (1.0f / 128.0f) + 1e-5f);

    float y0 = d0 * rstd * gg.x + be.x;
    float y1 = d1 * rstd * gg.y + be.y;
    float y2 = d2 * rstd * gg.z + be.z;
    float y3 = d3 * rstd * gg.w + be.w;
    float4 o4;
    o4.x = y0 / (1.0f + expf(-y0));
    o4.y = y1 / (1.0f + expf(-y1));
    o4.z = y2 / (1.0f + expf(-y2));
    o4.w = y3 / (1.0f + expf(-y3));

    const int b2 = row / n_out;
    const int nn = row % n_out;
    const float4 rr = *(const float4*)(
        res_in + ((size_t)b2 * (2 * n_out) + 2 * nn) * 128 + lane * 4);
    o4.x += rr.x; o4.y += rr.y; o4.z += rr.z; o4.w += rr.w;
    ((float4*)out)[(size_t)row * 32 + lane] = o4;
}

// ---------------------------------------------------------------------------
// Residual path (stage 1): res1[b,n,:] = ch[b,2n,:] @ Wres + bres
// ---------------------------------------------------------------------------
__global__ void __launch_bounds__(128) res_kernel(
    const float* __restrict__ ch, const float* __restrict__ Wres,
    const float* __restrict__ bres, float* __restrict__ res1)
{
    __shared__ float s_w[64 * 128];
    __shared__ float s_ch[8][64];
    const int tid = threadIdx.x;
    const int m_base = blockIdx.x * 64;
    const int b = m_base / 4096;
    const int n_base = m_base % 4096;

    for (int i = tid; i < 64 * 128 / 4; i += 128)
        ((float4*)s_w)[i] = ((const float4*)Wres)[i];
    __syncthreads();

    const float bias = __ldg(&bres[tid]);
    const int rr = tid >> 4, q = tid & 15;

    for (int g = 0; g < 8; g++) {
        const float* src = ch +
            ((size_t)b * 8192 + 2 * (n_base + g * 8 + rr)) * 64 + q * 4;
        *(float4*)&s_ch[rr][q * 4] = *(const float4*)src;
        __syncthreads();
        float acc[8];
#pragma unroll
        for (int t = 0; t < 8; t++) acc[t] = bias;
        for (int c = 0; c < 64; c++) {
            float wv = s_w[c * 128 + tid];
#pragma unroll
            for (int t = 0; t < 8; t++) acc[t] += s_ch[t][c] * wv;
        }
#pragma unroll
        for (int t = 0; t < 8; t++)
            res1[(size_t)(m_base + g * 8 + t) * 128 + tid] = acc[t];
        __syncthreads();
    }
}

// ---------------------------------------------------------------------------
__global__ void poscopy_kernel(const float* __restrict__ pos,
                               float* __restrict__ out)
{
    int i = blockIdx.x * blockDim.x + threadIdx.x;
    if (i < 2 * 2048 * 3) {
        int b = i / 6144;
        int rem = i - b * 6144;
        int n = rem / 3;
        int d = rem - n * 3;
        out[i] = pos[((size_t)b * 8192 + 4 * n) * 3 + d];
    }
}

// ---------------------------------------------------------------------------
extern "C" void kernel_launch(void* const* d_in, const int* in_sizes, int n_in,
                              void* d_out, int out_size)
{
    const float* pos  = (const float*)d_in[0];
    const float* ch   = (const float*)d_in[1];
    const float* W1   = (const float*)d_in[2];
    const float* b1   = (const float*)d_in[3];
    const float* Wres = (const float*)d_in[4];
    const float* bres = (const float*)d_in[5];
    const float* W2   = (const float*)d_in[6];
    const float* b2   = (const float*)d_in[7];
    const float* g1   = (const float*)d_in[8];
    const float* be1  = (const float*)d_in[9];
    const float* g2   = (const float*)d_in[10];
    const float* be2  = (const float*)d_in[11];
    float* out = (float*)d_out;

    int *knn1p, *knn2p;
    float *res1p, *partp;
    uint4 *w1p, *w2p;
    uint2 *chp, *c1p;
    cudaGetSymbolAddress((void**)&knn1p, g_knn1);
    cudaGetSymbolAddress((void**)&knn2p, g_knn2);
    cudaGetSymbolAddress((void**)&res1p, g_res1);
    cudaGetSymbolAddress((void**)&partp, g_part);
    cudaGetSymbolAddress((void**)&w1p, g_W1p);
    cudaGetSymbolAddress((void**)&w2p, g_W2p);
    cudaGetSymbolAddress((void**)&chp, g_chp);
    cudaGetSymbolAddress((void**)&c1p, g_ch1p);

    // dynamic smem: 2 A-planes (uint2) + 2 B-planes (uint4)
    constexpr int SMEM = 2 * 16 * 132 * 8 + 2 * 1024 * 16;   // 66560 B
    cudaFuncSetAttribute(gconv_mma<64, 4>,
                         cudaFuncAttributeMaxDynamicSharedMemorySize, SMEM);
    cudaFuncSetAttribute(gconv_mma<128, 8>,
                         cudaFuncAttributeMaxDynamicSharedMemorySize, SMEM);

    // prep: permuted/split planes
    split_kernel<<<1792, 256>>>(W1, W2, ch);
    // KNN (both stages, one launch)
    knn_kernel<<<1536, 256>>>(pos, knn1p, knn2p);
    // residual GEMM (stage 1)
    res_kernel<<<128, 128>>>(ch, Wres, bres, res1p);
    // conv1: split-K 4 -> partials -> combine (writes ch1 interleaved)
    gconv_mma<64, 4><<<dim3(64, 4), 256, SMEM>>>(
        chp, knn1p, w1p, partp, 8192, 4096, 8192);
    combine_mid<4><<<1024, 256>>>(partp, 8192, b1, g1, be1, c1p);
    // conv2: split-K 8 -> partials -> combine (+res, float out)
    gconv_mma<128, 8><<<dim3(32, 8), 256, SMEM>>>(
        c1p, knn2p, w2p, partp, 4096, 2048, 4096);
    combine_final<8><<<512, 256>>>(
        partp, 4096, b2, g2, be2, res1p, out + 2 * 2048 * 3, 2048);
    // pos output
    poscopy_kernel<<<48, 256>>>(pos, out);
}

// round 9
// speedup vs baseline: 1.1642x; 1.0714x over previous
#include <cuda_runtime.h>
#include <cstdint>
#include <cstddef>
#include <math.h>

// ---------------------------------------------------------------------------
// Scratch (device globals -- no allocation allowed)
// ---------------------------------------------------------------------------
__device__ int   g_knn1[2 * 4096 * 16];
__device__ int   g_knn2[2 * 2048 * 16];
__device__ float g_part[4194304];          // split-K partials (16MB)
__device__ uint4 g_W1p[65536];             // W1 fragment-permuted (1MB)
__device__ uint4 g_W2p[131072];            // W2 fragment-permuted (2MB)
__device__ uint2 g_chp[1048576];           // ch  interleaved tf32 hi/lo (8MB)
__device__ uint2 g_ch1p[1048576];          // ch1 interleaved tf32 hi/lo (8MB)

// ---------------------------------------------------------------------------
// helpers
// ---------------------------------------------------------------------------
__device__ __forceinline__ unsigned int to_tf32(float v) {
    unsigned int r;
    asm("cvt.rna.tf32.f32 %0, %1;" : "=r"(r) : "f"(v));
    return r;
}
__device__ __forceinline__ void split_tf32(float v, unsigned int& hi,
                                           unsigned int& lo) {
    hi = to_tf32(v);
    lo = to_tf32(v - __uint_as_float(hi));
}
__device__ __forceinline__ void mma_tf32(float c[4], const unsigned int a[4],
                                         unsigned int b0, unsigned int b1) {
    asm("mma.sync.aligned.m16n8k8.row.col.f32.tf32.tf32.f32 "
        "{%0,%1,%2,%3}, {%4,%5,%6,%7}, {%8,%9}, {%0,%1,%2,%3};"
        : "+f"(c[0]), "+f"(c[1]), "+f"(c[2]), "+f"(c[3])
        : "r"(a[0]), "r"(a[1]), "r"(a[2]), "r"(a[3]), "r"(b0), "r"(b1));
}
__device__ __forceinline__ unsigned long long pack2(float x, float y) {
    unsigned long long r;
    asm("mov.b64 %0, {%1, %2};" : "=l"(r) : "f"(x), "f"(y));
    return r;
}
__device__ __forceinline__ unsigned long long add2(unsigned long long a,
                                                   unsigned long long b) {
    unsigned long long r;
    asm("add.rn.f32x2 %0, %1, %2;" : "=l"(r) : "l"(a), "l"(b));
    return r;
}
__device__ __forceinline__ unsigned long long mul2(unsigned long long a,
                                                   unsigned long long b) {
    unsigned long long r;
    asm("mul.rn.f32x2 %0, %1, %2;" : "=l"(r) : "l"(a), "l"(b));
    return r;
}
__device__ __forceinline__ void cp_async8(unsigned int dst, const void* src) {
    asm volatile("cp.async.ca.shared.global [%0], [%1], 8;"
                 :: "r"(dst), "l"(src));
}
__device__ __forceinline__ void cp_async16(unsigned int dst, const void* src) {
    asm volatile("cp.async.cg.shared.global [%0], [%1], 16;"
                 :: "r"(dst), "l"(src));
}

// ---------------------------------------------------------------------------
// prep: one kernel, block-range dispatch:
//  blocks [0,1024)    : KNN stage 1
//  blocks [1024,1536) : KNN stage 2
//  blocks [1536,3376) : W1/W2 fragment-permute split, ch split, pos copy
// ---------------------------------------------------------------------------
__global__ void __launch_bounds__(256) prep_kernel(
    const float* __restrict__ pos, int* __restrict__ knn1,
    int* __restrict__ knn2,
    const float* __restrict__ W1, const float* __restrict__ W2,
    const float* __restrict__ ch, float* __restrict__ out)
{
    constexpr int TILE = 1024;
    __shared__ __align__(16) float sn[3 * TILE];

    const int tid = threadIdx.x;

    if (blockIdx.x >= 1536) {
        // ---------------- split / poscopy region ----------------
        int i = (blockIdx.x - 1536) * 256 + tid;
        if (i < 65536) {                               // W1p
            int p = i >> 9, n = (i >> 2) & 127, t = i & 3;
            int k0 = 8 * p + t;
            float v0 = __ldg(W1 + n * 1024 + k0);
            float v1 = __ldg(W1 + n * 1024 + k0 + 4);
            uint4 o;
            split_tf32(v0, o.x, o.z);
            split_tf32(v1, o.y, o.w);
            g_W1p[i] = o;
        } else if (i < 196608) {                       // W2p
            int j = i - 65536;
            int p = j >> 9, n = (j >> 2) & 127, t = j & 3;
            int k0 = 8 * p + t;
            float v0 = __ldg(W2 + n * 2048 + k0);
            float v1 = __ldg(W2 + n * 2048 + k0 + 4);
            uint4 o;
            split_tf32(v0, o.x, o.z);
            split_tf32(v1, o.y, o.w);
            g_W2p[j] = o;
        } else if (i < 458752) {                       // chp (4 floats/thr)
            int j = i - 196608;
            float4 v = __ldg((const float4*)ch + j);
            uint4 s0, s1;
            split_tf32(v.x, s0.x, s0.y);
            split_tf32(v.y, s0.z, s0.w);
            split_tf32(v.z, s1.x, s1.y);
            split_tf32(v.w, s1.z, s1.w);
            ((uint4*)g_chp)[2 * j]     = s0;
            ((uint4*)g_chp)[2 * j + 1] = s1;
        } else if (i < 471040) {                       // pos copy
            int j = i - 458752;
            int b = j / 6144;
            int rem = j - b * 6144;
            int n = rem / 3;
            int d = rem - n * 3;
            out[j] = pos[((size_t)b * 8192 + 4 * n) * 3 + d];
        }
        return;
    }

    // -------------------- KNN region --------------------
    const int warp = tid >> 5;
    const int lane = tid & 31;

    int pstride, n_in, n_out, center;
    int* outp;
    if (blockIdx.x < 1024) {
        pstride = 1; n_in = 8192; n_out = 4096; outp = knn1;
        center = blockIdx.x * 8 + warp;
    } else {
        pstride = 2; n_in = 4096; n_out = 2048; outp = knn2;
        center = (blockIdx.x - 1024) * 8 + warp;
    }
    const int b = center / n_out;
    const int n = center % n_out;

    const float* posb = pos + (size_t)b * 8192 * 3;
    const float cx = posb[(size_t)(n * 2 * pstride) * 3 + 0];
    const float cy = posb[(size_t)(n * 2 * pstride) * 3 + 1];
    const float cz = posb[(size_t)(n * 2 * pstride) * 3 + 2];
    const unsigned long long cxx = pack2(cx, cx);
    const unsigned long long cyy = pack2(cy, cy);
    const unsigned long long czz = pack2(cz, cz);

    unsigned long long lkey   = 0x7F800000FFFFFFFFull;
    unsigned long long thresh = 0x7F800000FFFFFFFFull;
    float tf = __int_as_float(0x7F800000);

    const int nTiles = n_in / TILE;
    float v[12];

#pragma unroll
    for (int k = 0; k < 4; k++) {
        int p = k * 256 + tid;
#pragma unroll
        for (int d = 0; d < 3; d++)
            v[3 * k + d] = __ldg(posb + (size_t)p * pstride * 3 + d);
    }

    for (int t = 0; t < nTiles; t++) {
#pragma unroll
        for (int k = 0; k < 4; k++) {
            int p = k * 256 + tid;
            sn[p]        = -v[3 * k];
            sn[p + 1024] = -v[3 * k + 1];
            sn[p + 2048] = -v[3 * k + 2];
        }
        __syncthreads();
        if (t + 1 < nTiles) {
            const int base = (t + 1) * TILE;
#pragma unroll
            for (int k = 0; k < 4; k++) {
                int p = base + k * 256 + tid;
#pragma unroll
                for (int d = 0; d < 3; d++)
                    v[3 * k + d] = __ldg(posb + (size_t)p * pstride * 3 + d);
            }
        }

        const int jbase = t * TILE;
#pragma unroll 4
        for (int it = 0; it < 16; ++it) {
            const int j = it * 64 + 2 * lane;
            unsigned long long nx = *(const unsigned long long*)(sn + j);
            unsigned long long ny = *(const unsigned long long*)(sn + 1024 + j);
            unsigned long long nz = *(const unsigned long long*)(sn + 2048 + j);
            unsigned long long ax = add2(cxx, nx);
            unsigned long long ay = add2(cyy, ny);
            unsigned long long az = add2(czz, nz);
            unsigned long long dp =
                add2(add2(mul2(ax, ax), mul2(ay, ay)), mul2(az, az));
            float d0, d1;
            asm("mov.b64 {%0, %1}, %2;" : "=f"(d0), "=f"(d1) : "l"(dp));
#pragma unroll
            for (int h = 0; h < 2; h++) {
                float dv = h ? d1 : d0;
                unsigned mask = __ballot_sync(0xffffffffu, dv <= tf);
                while (mask) {
                    const int src = __ffs(mask) - 1;
                    mask &= mask - 1;
                    float cd = __shfl_sync(0xffffffffu, dv, src);
                    unsigned idx = (unsigned)(jbase + it * 64 + 2 * src + h);
                    unsigned long long ck =
                        ((unsigned long long)__float_as_uint(cd) << 32) | idx;
                    if (ck < thresh) {
                        unsigned long long up =
                            __shfl_up_sync(0xffffffffu, lkey, 1);
                        bool keep = (lkey < ck);
                        unsigned long long ins =
                            (lane == 0 || up < ck) ? ck : up;
                        lkey = keep ? lkey : ins;
                        thresh = __shfl_sync(0xffffffffu, lkey, 15);
                        tf = __uint_as_float((unsigned)(thresh >> 32));
                    }
                }
            }
        }
        __syncthreads();
    }

    if (lane < 16)
        outp[(size_t)center * 16 + lane] =
            (int)(unsigned)(lkey & 0xffffffffull);
}

// ---------------------------------------------------------------------------
// Gathered-conv GEMM, 3xTF32 tensor cores, 4-stage cp.async ring (BK=8).
// A: cp.async(8B) gathered into interleaved hi/lo uint2 smem (stride 132,
//    conflict-free LDS.64 fragments).
// B: cp.async(16B) of the fragment-permuted W image; each consumer fragment
//    is ONE conflict-free LDS.128.
// 256 threads, BM=128 x BN=128, 8 warps (4M x 2N), split-K over neighbors.
// ---------------------------------------------------------------------------
template <int CIN, int NSPLIT>
__global__ void __launch_bounds__(256, 2)
gconv_mma(const uint2* __restrict__ chp, const int* __restrict__ knn,
          const uint4* __restrict__ Wp, float* __restrict__ part,
          int n_in, int n_out, int Mtot)
{
    constexpr int BM = 128, BN = 128, BK = 8, S2 = 132, STAGES = 4;
    constexpr int APLANE = BK * S2;          // uint2 units (1056)
    constexpr int BPLANE = 512;              // uint4 units per k8 panel
    constexpr int NPB = 16 / NSPLIT;
    constexpr int ITERS = NPB * CIN / BK;
    extern __shared__ __align__(16) unsigned char dynraw[];
    uint2* As2 = (uint2*)dynraw;                           // STAGES*APLANE
    uint4* Bs4 = (uint4*)(dynraw + STAGES * APLANE * 8);   // STAGES*BPLANE

    const int tid = threadIdx.x;
    const int split = blockIdx.y;
    const int m_base = blockIdx.x * BM;
    const int b = m_base / n_out;
    const int warp = tid >> 5, lane = tid & 31;
    const int g = lane >> 2, t = lane & 3;
    const int wm = (warp & 3) * 32, wn = (warp >> 2) * 64;

    const int arow = tid >> 1;
    const int aoff = (tid & 1) * 4;          // 4 kslots per thread (BK=8)
    const int* knnrow = knn + (size_t)(m_base + arow) * 16;
    const uint2* chb = chp + (size_t)b * n_in * CIN;
    const int kpan0 = (split * NPB * CIN) >> 3;   // starting 8-wide k panel

    const unsigned int abase =
        (unsigned int)__cvta_generic_to_shared(As2) + (aoff * S2 + arow) * 8;
    const unsigned int bbase =
        (unsigned int)__cvta_generic_to_shared(Bs4) + tid * 32;

    float acc[2][8][4];
#pragma unroll
    for (int i = 0; i < 2; i++)
#pragma unroll
        for (int j = 0; j < 8; j++)
#pragma unroll
            for (int k = 0; k < 4; k++) acc[i][j][k] = 0.0f;

    auto issue = [&](int it, int buf) {
        const int kn = split * NPB + (it * BK) / CIN;
        const int c0 = (it * BK) % CIN;
        const int j = __ldg(&knnrow[kn]);
        const uint2* srcA = chb + (size_t)j * CIN + c0 + aoff;
        const unsigned int dA = abase + buf * (APLANE * 8);
#pragma unroll
        for (int i = 0; i < 4; i++) cp_async8(dA + i * (S2 * 8), srcA + i);
        const uint4* srcB = Wp + ((size_t)(kpan0 + it) << 9) + tid * 2;
        const unsigned int dB = bbase + buf * (BPLANE * 16);
#pragma unroll
        for (int q = 0; q < 2; q++) cp_async16(dB + q * 16, srcB + q);
    };

    issue(0, 0); asm volatile("cp.async.commit_group;");
    issue(1, 1); asm volatile("cp.async.commit_group;");
    issue(2, 2); asm volatile("cp.async.commit_group;");

    for (int it = 0; it < ITERS; ++it) {
        asm volatile("cp.async.wait_group 2;");
        __syncthreads();
        if (it + 3 < ITERS) issue(it + 3, (it + 3) & 3);
        asm volatile("cp.async.commit_group;");

        const uint2* As = As2 + (it & 3) * APLANE;
        const uint4* Bs = Bs4 + (it & 3) * BPLANE;

        unsigned int Abf[2][4], Alf[2][4];
#pragma unroll
        for (int mt = 0; mt < 2; mt++) {
            const int r0 = wm + mt * 16 + g;
            uint2 a0 = As[t * S2 + r0];
            uint2 a1 = As[t * S2 + r0 + 8];
            uint2 a2 = As[(t + 4) * S2 + r0];
            uint2 a3 = As[(t + 4) * S2 + r0 + 8];
            Abf[mt][0] = a0.x; Alf[mt][0] = a0.y;
            Abf[mt][1] = a1.x; Alf[mt][1] = a1.y;
            Abf[mt][2] = a2.x; Alf[mt][2] = a2.y;
            Abf[mt][3] = a3.x; Alf[mt][3] = a3.y;
        }
#pragma unroll
        for (int nt = 0; nt < 8; nt++) {
            uint4 w = Bs[(wn + nt * 8 + g) * 4 + t];
#pragma unroll
            for (int mt = 0; mt < 2; mt++) {
                mma_tf32(acc[mt][nt], Abf[mt], w.x, w.y);
                mma_tf32(acc[mt][nt], Abf[mt], w.z, w.w);
                mma_tf32(acc[mt][nt], Alf[mt], w.x, w.y);
            }
        }
    }

    float* dst = part + ((size_t)split * Mtot + m_base) * BN;
#pragma unroll
    for (int mt = 0; mt < 2; mt++)
#pragma unroll
        for (int nt = 0; nt < 8; nt++) {
            const int r = wm + mt * 16 + g;
            const int c = wn + nt * 8 + 2 * t;
            *(float2*)(dst + (size_t)r * BN + c) =
                make_float2(acc[mt][nt][0], acc[mt][nt][1]);
            *(float2*)(dst + (size_t)(r + 8) * BN + c) =
                make_float2(acc[mt][nt][2], acc[mt][nt][3]);
        }
}

// ---------------------------------------------------------------------------
// combine (mid): sum partials + bias + LN + SiLU -> interleaved tf32 uint2
// ---------------------------------------------------------------------------
template <int NSPLIT>
__global__ void __launch_bounds__(256) combine_mid(
    const float* __restrict__ part, int M,
    const float* __restrict__ bias, const float* __restrict__ gamma,
    const float* __restrict__ beta, uint2* __restrict__ outp)
{
    const int lane = threadIdx.x & 31;
    const int row = blockIdx.x * 8 + (threadIdx.x >> 5);

    const float4* p4 = (const float4*)part;
    float4 x = p4[(size_t)row * 32 + lane];
#pragma unroll
    for (int s = 1; s < NSPLIT; s++) {
        float4 y = p4[((size_t)s * M + row) * 32 + lane];
        x.x += y.x; x.y += y.y; x.z += y.z; x.w += y.w;
    }
    float4 bb = *(const float4*)(bias + lane * 4);
    float4 gg = *(const float4*)(gamma + lane * 4);
    float4 be = *(const float4*)(beta + lane * 4);
    x.x += bb.x; x.y += bb.y; x.z += bb.z; x.w += bb.w;

    float s = x.x + x.y + x.z + x.w;
#pragma unroll
    for (int off = 16; off; off >>= 1) s += __shfl_xor_sync(~0u, s, off);
    float mu = s * (1.0f / 128.0f);
    float d0 = x.x - mu, d1 = x.y - mu, d2 = x.z - mu, d3 = x.w - mu;
    float s2 = d0 * d0 + d1 * d1 + d2 * d2 + d3 * d3;
#pragma unroll
    for (int off = 16; off; off >>= 1) s2 += __shfl_xor_sync(~0u, s2, off);
    float rstd = rsqrtf(s2 * (1.0f / 128.0f) + 1e-5f);

    float y0 = d0 * rstd * gg.x + be.x;
    float y1 = d1 * rstd * gg.y + be.y;
    float y2 = d2 * rstd * gg.z + be.z;
    float y3 = d3 * rstd * gg.w + be.w;
    y0 = y0 / (1.0f + expf(-y0));
    y1 = y1 / (1.0f + expf(-y1));
    y2 = y2 / (1.0f + expf(-y2));
    y3 = y3 / (1.0f + expf(-y3));

    uint4 s0, s1;
    split_tf32(y0, s0.x, s0.y);
    split_tf32(y1, s0.z, s0.w);
    split_tf32(y2, s1.x, s1.y);
    split_tf32(y3, s1.z, s1.w);
    ((uint4*)outp)[(size_t)row * 64 + lane * 2]     = s0;
    ((uint4*)outp)[(size_t)row * 64 + lane * 2 + 1] = s1;
}

// ---------------------------------------------------------------------------
// combine (final): sum partials + bias + LN + SiLU + FUSED residual GEMM.
// residual row m: bres + ch[b, 4*(m%n_out), :64] @ Wres  (Wres in smem).
// ---------------------------------------------------------------------------
template <int NSPLIT>
__global__ void __launch_bounds__(256) combine_final(
    const float* __restrict__ part, int M,
    const float* __restrict__ bias, const float* __restrict__ gamma,
    const float* __restrict__ beta, const float* __restrict__ ch,
    const float* __restrict__ Wres, const float* __restrict__ bres,
    float* __restrict__ out, int n_out)
{
    __shared__ float s_w[64 * 128];
    const int tid = threadIdx.x;
    const int lane = tid & 31;
    const int row = blockIdx.x * 8 + (tid >> 5);

    for (int i = tid; i < 2048; i += 256)
        ((float4*)s_w)[i] = ((const float4*)Wres)[i];
    __syncthreads();

    const int b2 = row / n_out;
    const int nn = row % n_out;

    // ---- residual GEMM: racc = bres + ch[b2, 4nn, :] @ Wres ----
    const float* chrow = ch + ((size_t)b2 * 8192 + 4 * (size_t)nn) * 64;
    float4 racc = *(const float4*)(bres + lane * 4);
#pragma unroll 8
    for (int k = 0; k < 64; k++) {
        float a = __ldg(chrow + k);
        float4 w = *(const float4*)(s_w + k * 128 + lane * 4);
        racc.x += a * w.x; racc.y += a * w.y;
        racc.z += a * w.z; racc.w += a * w.w;
    }

    // ---- split-K combine + bias + LN + SiLU ----
    const float4* p4 = (const float4*)part;
    float4 x = p4[(size_t)row * 32 + lane];
#pragma unroll
    for (int s = 1; s < NSPLIT; s++) {
        float4 y = p4[((size_t)s * M + row) * 32 + lane];
        x.x += y.x; x.y += y.y; x.z += y.z; x.w += y.w;
    }
    float4 bb = *(const float4*)(bias + lane * 4);
    float4 gg = *(const float4*)(gamma + lane * 4);
    float4 be = *(const float4*)(beta + lane * 4);
    x.x += bb.x; x.y += bb.y; x.z += bb.z; x.w += bb.w;

    float s = x.x + x.y + x.z + x.w;
#pragma unroll
    for (int off = 16; off; off >>= 1) s += __shfl_xor_sync(~0u, s, off);
    float mu = s * (1.0f / 128.0f);
    float d0 = x.x - mu, d1 = x.y - mu, d2 = x.z - mu, d3 = x.w - mu;
    float s2 = d0 * d0 + d1 * d1 + d2 * d2 + d3 * d3;
#pragma unroll
    for (int off = 16; off; off >>= 1) s2 += __shfl_xor_sync(~0u, s2, off);
    float rstd = rsqrtf(s2 * (1.0f / 128.0f) + 1e-5f);

    float y0 = d0 * rstd * gg.x + be.x;
    float y1 = d1 * rstd * gg.y + be.y;
    float y2 = d2 * rstd * gg.z + be.z;
    float y3 = d3 * rstd * gg.w + be.w;
    float4 o4;
    o4.x = y0 / (1.0f + expf(-y0)) + racc.x;
    o4.y = y1 / (1.0f + expf(-y1)) + racc.y;
    o4.z = y2 / (1.0f + expf(-y2)) + racc.z;
    o4.w = y3 / (1.0f + expf(-y3)) + racc.w;

    ((float4*)out)[(size_t)row * 32 + lane] = o4;
}

// ---------------------------------------------------------------------------
extern "C" void kernel_launch(void* const* d_in, const int* in_sizes, int n_in,
                              void* d_out, int out_size)
{
    const float* pos  = (const float*)d_in[0];
    const float* ch   = (const float*)d_in[1];
    const float* W1   = (const float*)d_in[2];
    const float* b1   = (const float*)d_in[3];
    const float* Wres = (const float*)d_in[4];
    const float* bres = (const float*)d_in[5];
    const float* W2   = (const float*)d_in[6];
    const float* b2   = (const float*)d_in[7];
    const float* g1   = (const float*)d_in[8];
    const float* be1  = (const float*)d_in[9];
    const float* g2   = (const float*)d_in[10];
    const float* be2  = (const float*)d_in[11];
    float* out = (float*)d_out;

    int *knn1p, *knn2p;
    float *partp;
    uint4 *w1p, *w2p;
    uint2 *chp, *c1p;
    cudaGetSymbolAddress((void**)&knn1p, g_knn1);
    cudaGetSymbolAddress((void**)&knn2p, g_knn2);
    cudaGetSymbolAddress((void**)&partp, g_part);
    cudaGetSymbolAddress((void**)&w1p, g_W1p);
    cudaGetSymbolAddress((void**)&w2p, g_W2p);
    cudaGetSymbolAddress((void**)&chp, g_chp);
    cudaGetSymbolAddress((void**)&c1p, g_ch1p);

    // dynamic smem: 4 stages x (A plane 8448B + B plane 8192B) = 66560 B
    constexpr int SMEM = 4 * (8 * 132 * 8 + 512 * 16);
    cudaFuncSetAttribute(gconv_mma<64, 4>,
                         cudaFuncAttributeMaxDynamicSharedMemorySize, SMEM);
    cudaFuncSetAttribute(gconv_mma<128, 8>,
                         cudaFuncAttributeMaxDynamicSharedMemorySize, SMEM);

    // fused prep: KNN (blocks 0..1535) + splits + poscopy (1536..3375)
    prep_kernel<<<3376, 256>>>(pos, knn1p, knn2p, W1, W2, ch, out);
    // conv1: split-K 4 -> partials -> combine (writes ch1 interleaved)
    gconv_mma<64, 4><<<dim3(64, 4), 256, SMEM>>>(
        chp, knn1p, w1p, partp, 8192, 4096, 8192);
    combine_mid<4><<<1024, 256>>>(partp, 8192, b1, g1, be1, c1p);
    // conv2: split-K 8 -> partials -> combine (+fused residual, float out)
    gconv_mma<128, 8><<<dim3(32, 8), 256, SMEM>>>(
        c1p, knn2p, w2p, partp, 4096, 2048, 4096);
    combine_final<8><<<512, 256>>>(
        partp, 4096, b2, g2, be2, ch, Wres, bres, out + 2 * 2048 * 3, 2048);
}

// round 10
// speedup vs baseline: 1.5466x; 1.3285x over previous
#include <cuda_runtime.h>
#include <cstdint>
#include <cstddef>
#include <math.h>

// ---------------------------------------------------------------------------
// Scratch (device globals -- no allocation allowed)
// ---------------------------------------------------------------------------
__device__ int   g_knn1[2 * 4096 * 16];
__device__ int   g_knn2[2 * 2048 * 16];
__device__ float g_part[4194304];          // split-K partials (16MB)
__device__ uint4 g_W1p[32768];             // W1 bf16 h/m fragment-permuted
__device__ uint4 g_W2p[65536];             // W2 bf16 h/m fragment-permuted
__device__ uint4 g_chp[262144];            // ch  packed bf16 h/m pairs (4MB)
__device__ uint4 g_ch1p[262144];           // ch1 packed bf16 h/m pairs (4MB)

// ---------------------------------------------------------------------------
// helpers
// ---------------------------------------------------------------------------
// pack two floats to bf16x2 (lo = a, hi = b), round-to-nearest
__device__ __forceinline__ unsigned int pack_bf16(float a, float b) {
    unsigned int r;
    asm("cvt.rn.bf16x2.f32 %0, %1, %2;" : "=r"(r) : "f"(b), "f"(a));
    return r;
}
// split (v0,v1) into h-pair and m-pair (v = h + m, both bf16)
__device__ __forceinline__ void split_pair(float v0, float v1,
                                           unsigned int& hp, unsigned int& mp) {
    hp = pack_bf16(v0, v1);
    float h0 = __uint_as_float(hp << 16);
    float h1 = __uint_as_float(hp & 0xffff0000u);
    mp = pack_bf16(v0 - h0, v1 - h1);
}
__device__ __forceinline__ void mma_bf16(float c[4], const unsigned int a[4],
                                         unsigned int b0, unsigned int b1) {
    asm("mma.sync.aligned.m16n8k16.row.col.f32.bf16.bf16.f32 "
        "{%0,%1,%2,%3}, {%4,%5,%6,%7}, {%8,%9}, {%0,%1,%2,%3};"
        : "+f"(c[0]), "+f"(c[1]), "+f"(c[2]), "+f"(c[3])
        : "r"(a[0]), "r"(a[1]), "r"(a[2]), "r"(a[3]), "r"(b0), "r"(b1));
}
__device__ __forceinline__ unsigned long long pack2(float x, float y) {
    unsigned long long r;
    asm("mov.b64 %0, {%1, %2};" : "=l"(r) : "f"(x), "f"(y));
    return r;
}
__device__ __forceinline__ unsigned long long add2(unsigned long long a,
                                                   unsigned long long b) {
    unsigned long long r;
    asm("add.rn.f32x2 %0, %1, %2;" : "=l"(r) : "l"(a), "l"(b));
    return r;
}
__device__ __forceinline__ unsigned long long mul2(unsigned long long a,
                                                   unsigned long long b) {
    unsigned long long r;
    asm("mul.rn.f32x2 %0, %1, %2;" : "=l"(r) : "l"(a), "l"(b));
    return r;
}
__device__ __forceinline__ void cp_async8(unsigned int dst, const void* src) {
    asm volatile("cp.async.ca.shared.global [%0], [%1], 8;"
                 :: "r"(dst), "l"(src));
}
__device__ __forceinline__ void cp_async16(unsigned int dst, const void* src) {
    asm volatile("cp.async.cg.shared.global [%0], [%1], 16;"
                 :: "r"(dst), "l"(src));
}

// ---------------------------------------------------------------------------
// prep: one kernel, block-range dispatch:
//  blocks [0,1024)    : KNN stage 1
//  blocks [1024,1536) : KNN stage 2
//  blocks [1536,2992) : W1/W2 bf16 fragment-permute, ch split, pos copy
// W pack item (panel p, col n, t): uint4 {h(16p+2t)|h(+1)<<16,
//   h(16p+2t+8)|h(+9)<<16, m-pair0, m-pair1}  (B frag for m16n8k16)
// ---------------------------------------------------------------------------
__global__ void __launch_bounds__(256) prep_kernel(
    const float* __restrict__ pos, int* __restrict__ knn1,
    int* __restrict__ knn2,
    const float* __restrict__ W1, const float* __restrict__ W2,
    const float* __restrict__ ch, float* __restrict__ out)
{
    constexpr int TILE = 1024;
    __shared__ __align__(16) float sn[3 * TILE];

    const int tid = threadIdx.x;

    if (blockIdx.x >= 1536) {
        int i = (blockIdx.x - 1536) * 256 + tid;
        if (i < 32768) {                               // W1p
            int p = i >> 9, n = (i >> 2) & 127, t = i & 3;
            int k0 = 16 * p + 2 * t;
            float v0 = __ldg(W1 + n * 1024 + k0);
            float v1 = __ldg(W1 + n * 1024 + k0 + 1);
            float v2 = __ldg(W1 + n * 1024 + k0 + 8);
            float v3 = __ldg(W1 + n * 1024 + k0 + 9);
            uint4 o;
            split_pair(v0, v1, o.x, o.z);
            split_pair(v2, v3, o.y, o.w);
            g_W1p[i] = o;
        } else if (i < 98304) {                        // W2p
            int j = i - 32768;
            int p = j >> 9, n = (j >> 2) & 127, t = j & 3;
            int k0 = 16 * p + 2 * t;
            float v0 = __ldg(W2 + n * 2048 + k0);
            float v1 = __ldg(W2 + n * 2048 + k0 + 1);
            float v2 = __ldg(W2 + n * 2048 + k0 + 8);
            float v3 = __ldg(W2 + n * 2048 + k0 + 9);
            uint4 o;
            split_pair(v0, v1, o.x, o.z);
            split_pair(v2, v3, o.y, o.w);
            g_W2p[j] = o;
        } else if (i < 360448) {                       // chp (4 floats/thr)
            int j = i - 98304;
            float4 v = __ldg((const float4*)ch + j);
            uint4 o;
            split_pair(v.x, v.y, o.x, o.y);            // {hp0, mp0}
            split_pair(v.z, v.w, o.z, o.w);            // {hp1, mp1}
            g_chp[j] = o;
        } else if (i < 372736) {                       // pos copy
            int j = i - 360448;
            int b = j / 6144;
            int rem = j - b * 6144;
            int n = rem / 3;
            int d = rem - n * 3;
            out[j] = pos[((size_t)b * 8192 + 4 * n) * 3 + d];
        }
        return;
    }

    // -------------------- KNN region --------------------
    const int warp = tid >> 5;
    const int lane = tid & 31;

    int pstride, n_in, n_out, center;
    int* outp;
    if (blockIdx.x < 1024) {
        pstride = 1; n_in = 8192; n_out = 4096; outp = knn1;
        center = blockIdx.x * 8 + warp;
    } else {
        pstride = 2; n_in = 4096; n_out = 2048; outp = knn2;
        center = (blockIdx.x - 1024) * 8 + warp;
    }
    const int b = center / n_out;
    const int n = center % n_out;

    const float* posb = pos + (size_t)b * 8192 * 3;
    const float cx = posb[(size_t)(n * 2 * pstride) * 3 + 0];
    const float cy = posb[(size_t)(n * 2 * pstride) * 3 + 1];
    const float cz = posb[(size_t)(n * 2 * pstride) * 3 + 2];
    const unsigned long long cxx = pack2(cx, cx);
    const unsigned long long cyy = pack2(cy, cy);
    const unsigned long long czz = pack2(cz, cz);

    unsigned long long lkey   = 0x7F800000FFFFFFFFull;
    unsigned long long thresh = 0x7F800000FFFFFFFFull;
    float tf = __int_as_float(0x7F800000);

    const int nTiles = n_in / TILE;
    float v[12];

#pragma unroll
    for (int k = 0; k < 4; k++) {
        int p = k * 256 + tid;
#pragma unroll
        for (int d = 0; d < 3; d++)
            v[3 * k + d] = __ldg(posb + (size_t)p * pstride * 3 + d);
    }

    for (int t = 0; t < nTiles; t++) {
#pragma unroll
        for (int k = 0; k < 4; k++) {
            int p = k * 256 + tid;
            sn[p]        = -v[3 * k];
            sn[p + 1024] = -v[3 * k + 1];
            sn[p + 2048] = -v[3 * k + 2];
        }
        __syncthreads();
        if (t + 1 < nTiles) {
            const int base = (t + 1) * TILE;
#pragma unroll
            for (int k = 0; k < 4; k++) {
                int p = base + k * 256 + tid;
#pragma unroll
                for (int d = 0; d < 3; d++)
                    v[3 * k + d] = __ldg(posb + (size_t)p * pstride * 3 + d);
            }
        }

        const int jbase = t * TILE;
#pragma unroll 4
        for (int it = 0; it < 16; ++it) {
            const int j = it * 64 + 2 * lane;
            unsigned long long nx = *(const unsigned long long*)(sn + j);
            unsigned long long ny = *(const unsigned long long*)(sn + 1024 + j);
            unsigned long long nz = *(const unsigned long long*)(sn + 2048 + j);
            unsigned long long ax = add2(cxx, nx);
            unsigned long long ay = add2(cyy, ny);
            unsigned long long az = add2(czz, nz);
            unsigned long long dp =
                add2(add2(mul2(ax, ax), mul2(ay, ay)), mul2(az, az));
            float d0, d1;
            asm("mov.b64 {%0, %1}, %2;" : "=f"(d0), "=f"(d1) : "l"(dp));
#pragma unroll
            for (int h = 0; h < 2; h++) {
                float dv = h ? d1 : d0;
                unsigned mask = __ballot_sync(0xffffffffu, dv <= tf);
                while (mask) {
                    const int src = __ffs(mask) - 1;
                    mask &= mask - 1;
                    float cd = __shfl_sync(0xffffffffu, dv, src);
                    unsigned idx = (unsigned)(jbase + it * 64 + 2 * src + h);
                    unsigned long long ck =
                        ((unsigned long long)__float_as_uint(cd) << 32) | idx;
                    if (ck < thresh) {
                        unsigned long long up =
                            __shfl_up_sync(0xffffffffu, lkey, 1);
                        bool keep = (lkey < ck);
                        unsigned long long ins =
                            (lane == 0 || up < ck) ? ck : up;
                        lkey = keep ? lkey : ins;
                        thresh = __shfl_sync(0xffffffffu, lkey, 15);
                        tf = __uint_as_float((unsigned)(thresh >> 32));
                    }
                }
            }
        }
        __syncthreads();
    }

    if (lane < 16)
        outp[(size_t)center * 16 + lane] =
            (int)(unsigned)(lkey & 0xffffffffull);
}

// ---------------------------------------------------------------------------
// Gathered-conv GEMM, 3xBF16 (h+m split) m16n8k16 tensor cores, 4-stage
// cp.async ring (BK=16).
// A: cp.async(8B) gathered {h-pair, m-pair} uint2 smem, [kpair][row],
//    stride 132 -> conflict-free LDS.64 fragments.
// B: cp.async(16B) fragment-permuted W; one LDS.128 = both planes' frags.
// 256 threads, BM=128 x BN=128, 8 warps (4M x 2N), split-K over neighbors.
// ---------------------------------------------------------------------------
template <int CIN, int NSPLIT>
__global__ void __launch_bounds__(256, 2)
gconv_mma(const uint2* __restrict__ chp, const int* __restrict__ knn,
          const uint4* __restrict__ Wp, float* __restrict__ part,
          int n_in, int n_out, int Mtot)
{
    constexpr int BM = 128, BN = 128, BK = 16, S2 = 132, STAGES = 4;
    constexpr int APLANE = 8 * S2;           // 8 kpairs x 132 rows (uint2)
    constexpr int BPLANE = 512;              // uint4 per k16 panel
    constexpr int NPB = 16 / NSPLIT;
    constexpr int ITERS = NPB * CIN / BK;
    constexpr int CIN2 = CIN / 2;            // uint2 per row
    extern __shared__ __align__(16) unsigned char dynraw[];
    uint2* As2 = (uint2*)dynraw;                           // STAGES*APLANE
    uint4* Bs4 = (uint4*)(dynraw + STAGES * APLANE * 8);   // STAGES*BPLANE

    const int tid = threadIdx.x;
    const int split = blockIdx.y;
    const int m_base = blockIdx.x * BM;
    const int b = m_base / n_out;
    const int warp = tid >> 5, lane = tid & 31;
    const int g = lane >> 2, t = lane & 3;
    const int wm = (warp & 3) * 32, wn = (warp >> 2) * 64;

    const int arow = tid >> 1;
    const int ahalf = (tid & 1) * 4;         // kpair half (0 or 4)
    const int* knnrow = knn + (size_t)(m_base + arow) * 16;
    const uint2* chb = chp + (size_t)b * n_in * CIN2;
    const int kpan0 = (split * NPB * CIN) >> 4;   // 16-wide k panels

    const unsigned int abase =
        (unsigned int)__cvta_generic_to_shared(As2) + (ahalf * S2 + arow) * 8;
    const unsigned int bbase =
        (unsigned int)__cvta_generic_to_shared(Bs4) + tid * 32;

    float acc[2][8][4];
#pragma unroll
    for (int i = 0; i < 2; i++)
#pragma unroll
        for (int j = 0; j < 8; j++)
#pragma unroll
            for (int k = 0; k < 4; k++) acc[i][j][k] = 0.0f;

    auto issue = [&](int it, int buf) {
        const int kn = split * NPB + (it * BK) / CIN;
        const int c0 = ((it * BK) % CIN) >> 1;   // uint2 offset in row
        const int j = __ldg(&knnrow[kn]);
        const uint2* srcA = chb + (size_t)j * CIN2 + c0 + ahalf;
        const unsigned int dA = abase + buf * (APLANE * 8);
#pragma unroll
        for (int i = 0; i < 4; i++) cp_async8(dA + i * (S2 * 8), srcA + i);
        const uint4* srcB = Wp + ((size_t)(kpan0 + it) << 9) + tid * 2;
        const unsigned int dB = bbase + buf * (BPLANE * 16);
#pragma unroll
        for (int q = 0; q < 2; q++) cp_async16(dB + q * 16, srcB + q);
    };

    issue(0, 0); asm volatile("cp.async.commit_group;");
    issue(1, 1); asm volatile("cp.async.commit_group;");
    issue(2, 2); asm volatile("cp.async.commit_group;");

    for (int it = 0; it < ITERS; ++it) {
        asm volatile("cp.async.wait_group 2;");
        __syncthreads();
        if (it + 3 < ITERS) issue(it + 3, (it + 3) & 3);
        asm volatile("cp.async.commit_group;");

        const uint2* As = As2 + (it & 3) * APLANE;
        const uint4* Bs = Bs4 + (it & 3) * BPLANE;

        unsigned int Ah[2][4], Am[2][4];
#pragma unroll
        for (int mt = 0; mt < 2; mt++) {
            const int r0 = wm + mt * 16 + g;
            uint2 a0 = As[t * S2 + r0];            // (row g,   kpair t)
            uint2 a1 = As[t * S2 + r0 + 8];        // (row g+8, kpair t)
            uint2 a2 = As[(t + 4) * S2 + r0];      // (row g,   kpair t+4)
            uint2 a3 = As[(t + 4) * S2 + r0 + 8];  // (row g+8, kpair t+4)
            Ah[mt][0] = a0.x; Am[mt][0] = a0.y;
            Ah[mt][1] = a1.x; Am[mt][1] = a1.y;
            Ah[mt][2] = a2.x; Am[mt][2] = a2.y;
            Ah[mt][3] = a3.x; Am[mt][3] = a3.y;
        }
#pragma unroll
        for (int nt = 0; nt < 8; nt++) {
            uint4 w = Bs[(wn + nt * 8 + g) * 4 + t];   // {bh0,bh1,bm0,bm1}
#pragma unroll
            for (int mt = 0; mt < 2; mt++) {
                mma_bf16(acc[mt][nt], Ah[mt], w.x, w.y);
                mma_bf16(acc[mt][nt], Ah[mt], w.z, w.w);
                mma_bf16(acc[mt][nt], Am[mt], w.x, w.y);
            }
        }
    }

    float* dst = part + ((size_t)split * Mtot + m_base) * BN;
#pragma unroll
    for (int mt = 0; mt < 2; mt++)
#pragma unroll
        for (int nt = 0; nt < 8; nt++) {
            const int r = wm + mt * 16 + g;
            const int c = wn + nt * 8 + 2 * t;
            *(float2*)(dst + (size_t)r * BN + c) =
                make_float2(acc[mt][nt][0], acc[mt][nt][1]);
            *(float2*)(dst + (size_t)(r + 8) * BN + c) =
                make_float2(acc[mt][nt][2], acc[mt][nt][3]);
        }
}

// ---------------------------------------------------------------------------
// combine (mid): sum partials + bias + LN + SiLU -> packed bf16 h/m pairs
// ---------------------------------------------------------------------------
template <int NSPLIT>
__global__ void __launch_bounds__(256) combine_mid(
    const float* __restrict__ part, int M,
    const float* __restrict__ bias, const float* __restrict__ gamma,
    const float* __restrict__ beta, uint4* __restrict__ outp)
{
    const int lane = threadIdx.x & 31;
    const int row = blockIdx.x * 8 + (threadIdx.x >> 5);

    const float4* p4 = (const float4*)part;
    float4 x = p4[(size_t)row * 32 + lane];
#pragma unroll
    for (int s = 1; s < NSPLIT; s++) {
        float4 y = p4[((size_t)s * M + row) * 32 + lane];
        x.x += y.x; x.y += y.y; x.z += y.z; x.w += y.w;
    }
    float4 bb = *(const float4*)(bias + lane * 4);
    float4 gg = *(const float4*)(gamma + lane * 4);
    float4 be = *(const float4*)(beta + lane * 4);
    x.x += bb.x; x.y += bb.y; x.z += bb.z; x.w += bb.w;

    float s = x.x + x.y + x.z + x.w;
#pragma unroll
    for (int off = 16; off; off >>= 1) s += __shfl_xor_sync(~0u, s, off);
    float mu = s * (1.0f / 128.0f);
    float d0 = x.x - mu, d1 = x.y - mu, d2 = x.z - mu, d3 = x.w - mu;
    float s2 = d0 * d0 + d1 * d1 + d2 * d2 + d3 * d3;
#pragma unroll
    for (int off = 16; off; off >>= 1) s2 += __shfl_xor_sync(~0u, s2, off);
    float rstd = rsqrtf(s2 * (1.0f / 128.0f) + 1e-5f);

    float y0 = d0 * rstd * gg.x + be.x;
    float y1 = d1 * rstd * gg.y + be.y;
    float y2 = d2 * rstd * gg.z + be.z;
    float y3 = d3 * rstd * gg.w + be.w;
    y0 = y0 / (1.0f + expf(-y0));
    y1 = y1 / (1.0f + expf(-y1));
    y2 = y2 / (1.0f + expf(-y2));
    y3 = y3 / (1.0f + expf(-y3));

    uint4 o;
    split_pair(y0, y1, o.x, o.y);
    split_pair(y2, y3, o.z, o.w);
    outp[(size_t)row * 32 + lane] = o;
}

// ---------------------------------------------------------------------------
// combine (final): sum partials + bias + LN + SiLU + FUSED residual GEMM.
// ---------------------------------------------------------------------------
template <int NSPLIT>
__global__ void __launch_bounds__(256) combine_final(
    const float* __restrict__ part, int M,
    const float* __restrict__ bias, const float* __restrict__ gamma,
    const float* __restrict__ beta, const float* __restrict__ ch,
    const float* __restrict__ Wres, const float* __restrict__ bres,
    float* __restrict__ out, int n_out)
{
    __shared__ float s_w[64 * 128];
    const int tid = threadIdx.x;
    const int lane = tid & 31;
    const int row = blockIdx.x * 8 + (tid >> 5);

    for (int i = tid; i < 2048; i += 256)
        ((float4*)s_w)[i] = ((const float4*)Wres)[i];
    __syncthreads();

    const int b2 = row / n_out;
    const int nn = row % n_out;

    const float* chrow = ch + ((size_t)b2 * 8192 + 4 * (size_t)nn) * 64;
    float4 racc = *(const float4*)(bres + lane * 4);
#pragma unroll 8
    for (int k = 0; k < 64; k++) {
        float a = __ldg(chrow + k);
        float4 w = *(const float4*)(s_w + k * 128 + lane * 4);
        racc.x += a * w.x; racc.y += a * w.y;
        racc.z += a * w.z; racc.w += a * w.w;
    }

    const float4* p4 = (const float4*)part;
    float4 x = p4[(size_t)row * 32 + lane];
#pragma unroll
    for (int s = 1; s < NSPLIT; s++) {
        float4 y = p4[((size_t)s * M + row) * 32 + lane];
        x.x += y.x; x.y += y.y; x.z += y.z; x.w += y.w;
    }
    float4 bb = *(const float4*)(bias + lane * 4);
    float4 gg = *(const float4*)(gamma + lane * 4);
    float4 be = *(const float4*)(beta + lane * 4);
    x.x += bb.x; x.y += bb.y; x.z += bb.z; x.w += bb.w;

    float s = x.x + x.y + x.z + x.w;
#pragma unroll
    for (int off = 16; off; off >>= 1) s += __shfl_xor_sync(~0u, s, off);
    float mu = s * (1.0f / 128.0f);
    float d0 = x.x - mu, d1 = x.y - mu, d2 = x.z - mu, d3 = x.w - mu;
    float s2 = d0 * d0 + d1 * d1 + d2 * d2 + d3 * d3;
#pragma unroll
    for (int off = 16; off; off >>= 1) s2 += __shfl_xor_sync(~0u, s2, off);
    float rstd = rsqrtf(s2 * (1.0f / 128.0f) + 1e-5f);

    float y0 = d0 * rstd * gg.x + be.x;
    float y1 = d1 * rstd * gg.y + be.y;
    float y2 = d2 * rstd * gg.z + be.z;
    float y3 = d3 * rstd * gg.w + be.w;
    float4 o4;
    o4.x = y0 / (1.0f + expf(-y0)) + racc.x;
    o4.y = y1 / (1.0f + expf(-y1)) + racc.y;
    o4.z = y2 / (1.0f + expf(-y2)) + racc.z;
    o4.w = y3 / (1.0f + expf(-y3)) + racc.w;

    ((float4*)out)[(size_t)row * 32 + lane] = o4;
}

// ---------------------------------------------------------------------------
extern "C" void kernel_launch(void* const* d_in, const int* in_sizes, int n_in,
                              void* d_out, int out_size)
{
    const float* pos  = (const float*)d_in[0];
    const float* ch   = (const float*)d_in[1];
    const float* W1   = (const float*)d_in[2];
    const float* b1   = (const float*)d_in[3];
    const float* Wres = (const float*)d_in[4];
    const float* bres = (const float*)d_in[5];
    const float* W2   = (const float*)d_in[6];
    const float* b2   = (const float*)d_in[7];
    const float* g1   = (const float*)d_in[8];
    const float* be1  = (const float*)d_in[9];
    const float* g2   = (const float*)d_in[10];
    const float* be2  = (const float*)d_in[11];
    float* out = (float*)d_out;

    int *knn1p, *knn2p;
    float *partp;
    uint4 *w1p, *w2p, *chp, *c1p;
    cudaGetSymbolAddress((void**)&knn1p, g_knn1);
    cudaGetSymbolAddress((void**)&knn2p, g_knn2);
    cudaGetSymbolAddress((void**)&partp, g_part);
    cudaGetSymbolAddress((void**)&w1p, g_W1p);
    cudaGetSymbolAddress((void**)&w2p, g_W2p);
    cudaGetSymbolAddress((void**)&chp, g_chp);
    cudaGetSymbolAddress((void**)&c1p, g_ch1p);

    // dynamic smem: 4 stages x (A 8448B + B 8192B) = 66560 B
    constexpr int SMEM = 4 * (8 * 132 * 8 + 512 * 16);
    cudaFuncSetAttribute(gconv_mma<64, 4>,
                         cudaFuncAttributeMaxDynamicSharedMemorySize, SMEM);
    cudaFuncSetAttribute(gconv_mma<128, 8>,
                         cudaFuncAttributeMaxDynamicSharedMemorySize, SMEM);

    // fused prep: KNN (blocks 0..1535) + splits + poscopy (1536..2991)
    prep_kernel<<<2992, 256>>>(pos, knn1p, knn2p, W1, W2, ch, out);
    // conv1: split-K 4 -> partials -> combine (writes ch1 packed)
    gconv_mma<64, 4><<<dim3(64, 4), 256, SMEM>>>(
        (const uint2*)chp, knn1p, w1p, partp, 8192, 4096, 8192);
    combine_mid<4><<<1024, 256>>>(partp, 8192, b1, g1, be1, c1p);
    // conv2: split-K 8 -> partials -> combine (+fused residual, float out)
    gconv_mma<128, 8><<<dim3(32, 8), 256, SMEM>>>(
        (const uint2*)c1p, knn2p, w2p, partp, 4096, 2048, 4096);
    combine_final<8><<<512, 256>>>(
        partp, 4096, b2, g2, be2, ch, Wres, bres, out + 2 * 2048 * 3, 2048);
}